// round 4
// baseline (speedup 1.0000x reference)
#include <cuda_runtime.h>
#include <cuda_bf16.h>
#include <math.h>
#include <stdint.h>

#define NN 50000
#define NE 800000

// ---------------- scratch (device globals) ----------------
__device__ float g_xh[NN * 128], g_xl[NN * 128];
__device__ float g_gxh[NN * 128], g_gxl[NN * 128];
__device__ float g_hr[NN * 512];                           // [res | h] fused layer out
__device__ float g_z1h[NN * 256], g_z1l[NN * 256];
__device__ float g_z2h[NN * 256], g_z2l[NN * 256];
__device__ float g_t64h[NN * 64], g_t64l[NN * 64];
__device__ float g_zself[NN * 64];
__device__ float g_h3[NN * 64];
__device__ float g_asrc[NN * 4];
__device__ float g_adst[NN * 4];
__device__ float g_loop[NN];
__device__ float g_easum[NN];
__device__ int   g_deg[NN];
__device__ int   g_rowstart[NN];
__device__ int   g_cursor[NN];
__device__ int   g_csr[NE];
__device__ float g_ch[4];
__device__ int   g_total;
__device__ float g_wfa_h[128 * 128], g_wfa_l[128 * 128];
__device__ float g_wb1_h[128 * 512], g_wb1_l[128 * 512];
__device__ float g_wb2_h[256 * 512], g_wb2_l[256 * 512];
__device__ float g_w3_h[256 * 64],  g_w3_l[256 * 64];
__device__ float g_wf1_h[128 * 64], g_wf1_l[128 * 64];
__device__ float g_wf2_h[64 * 64],  g_wf2_l[64 * 64];
__device__ float g_bb1[512], g_bb2[512];

__device__ __forceinline__ float sigf(float x) { return 1.f / (1.f + __expf(-x)); }

__device__ __forceinline__ void tf32_split(float x, float& hi, float& lo) {
    uint32_t uh;
    asm("cvt.rna.tf32.f32 %0, %1;" : "=r"(uh) : "f"(x));
    hi = __uint_as_float(uh);
    float r = x - hi;
    uint32_t ul;
    asm("cvt.rna.tf32.f32 %0, %1;" : "=r"(ul) : "f"(r));
    lo = __uint_as_float(ul);
}

__device__ __forceinline__ void mma_tf32(float* c, const uint32_t* a, const uint32_t* b) {
    asm volatile(
        "mma.sync.aligned.m16n8k8.row.col.f32.tf32.tf32.f32 "
        "{%0,%1,%2,%3}, {%4,%5,%6,%7}, {%8,%9}, {%0,%1,%2,%3};\n"
        : "+f"(c[0]), "+f"(c[1]), "+f"(c[2]), "+f"(c[3])
        : "r"(a[0]), "r"(a[1]), "r"(a[2]), "r"(a[3]), "r"(b[0]), "r"(b[1]));
}

// ---------------- pack / split kernels ----------------
__global__ void split_kernel(const float* __restrict__ s, float* __restrict__ dh,
                             float* __restrict__ dl, int n) {
    int i = blockIdx.x * blockDim.x + threadIdx.x;
    if (i < n) { float h, l; tf32_split(s[i], h, l); dh[i] = h; dl[i] = l; }
}
__global__ void fusepack_kernel(const float* __restrict__ A, const float* __restrict__ B,
                                float* __restrict__ dh, float* __restrict__ dl,
                                int rows, int half) {
    int i = blockIdx.x * blockDim.x + threadIdx.x;
    int tot = rows * 2 * half;
    if (i < tot) {
        int r = i / (2 * half), c = i % (2 * half);
        float v = (c < half) ? A[r * half + c] : B[r * half + c - half];
        float h, l; tf32_split(v, h, l); dh[i] = h; dl[i] = l;
    }
}
__global__ void biaspack_kernel(const float* __restrict__ r1b, const float* __restrict__ r2b) {
    int i = blockIdx.x * blockDim.x + threadIdx.x;
    if (i < 512) {
        g_bb1[i] = (i < 256) ? r1b[i] : 0.f;
        g_bb2[i] = (i < 256) ? r2b[i] : 0.f;
    }
}

// ---------------- TF32 GEMM, float2-interleaved hi/lo fragments -------------
#define EP_NONE 0
#define EP_GATE 1
#define EP_RELU 2

template <int EP, bool SPLITOUT, bool WRITEC>
__global__ __launch_bounds__(256) void gemm3(
    const float* __restrict__ Agh, const float* __restrict__ Agl,
    const float* __restrict__ Bgh, const float* __restrict__ Bgl,
    const float* __restrict__ bias, const float* __restrict__ gateA,
    float* __restrict__ C, float* __restrict__ Ch, float* __restrict__ Cl,
    int M, int K, int N) {
    __shared__ float2 As[128][22];   // [m][k] = (hi,lo), stride 22 pads conflicts
    __shared__ float2 Bs[64][22];    // [n][k]
    const int bm = blockIdx.y * 128, bn = blockIdx.x * 64;
    const int tid = threadIdx.x, lane = tid & 31, wid = tid >> 5;
    const int wm = wid >> 1, wn = wid & 1;
    const int lg = lane >> 2, lt = lane & 3;
    const int ar0 = tid >> 2, as0 = (tid & 3) * 4;
    const int bkk = tid >> 4, bn4 = (tid & 15) * 4;

    float acc[2][4][4];
#pragma unroll
    for (int mt = 0; mt < 2; mt++)
#pragma unroll
        for (int nt = 0; nt < 4; nt++)
#pragma unroll
            for (int j = 0; j < 4; j++) acc[mt][nt][j] = 0.f;

    float4 rah[2], ral[2], rbh, rbl;
    const float4 z4 = make_float4(0.f, 0.f, 0.f, 0.f);

#pragma unroll
    for (int t = 0; t < 2; t++) {
        int r = ar0 + t * 64;
        if (bm + r < M) {
            rah[t] = *(const float4*)&Agh[(size_t)(bm + r) * K + as0];
            ral[t] = *(const float4*)&Agl[(size_t)(bm + r) * K + as0];
        } else { rah[t] = z4; ral[t] = z4; }
    }
    rbh = *(const float4*)&Bgh[(size_t)bkk * N + bn + bn4];
    rbl = *(const float4*)&Bgl[(size_t)bkk * N + bn + bn4];

    for (int k0 = 0; k0 < K; k0 += 16) {
#pragma unroll
        for (int t = 0; t < 2; t++) {
            int r = ar0 + t * 64;
            As[r][as0 + 0] = make_float2(rah[t].x, ral[t].x);
            As[r][as0 + 1] = make_float2(rah[t].y, ral[t].y);
            As[r][as0 + 2] = make_float2(rah[t].z, ral[t].z);
            As[r][as0 + 3] = make_float2(rah[t].w, ral[t].w);
        }
        Bs[bn4 + 0][bkk] = make_float2(rbh.x, rbl.x);
        Bs[bn4 + 1][bkk] = make_float2(rbh.y, rbl.y);
        Bs[bn4 + 2][bkk] = make_float2(rbh.z, rbl.z);
        Bs[bn4 + 3][bkk] = make_float2(rbh.w, rbl.w);
        __syncthreads();
        if (k0 + 16 < K) {
            int kn = k0 + 16;
#pragma unroll
            for (int t = 0; t < 2; t++) {
                int r = ar0 + t * 64;
                if (bm + r < M) {
                    rah[t] = *(const float4*)&Agh[(size_t)(bm + r) * K + kn + as0];
                    ral[t] = *(const float4*)&Agl[(size_t)(bm + r) * K + kn + as0];
                } else { rah[t] = z4; ral[t] = z4; }
            }
            rbh = *(const float4*)&Bgh[(size_t)(kn + bkk) * N + bn + bn4];
            rbl = *(const float4*)&Bgl[(size_t)(kn + bkk) * N + bn + bn4];
        }
#pragma unroll
        for (int ks = 0; ks < 16; ks += 8) {
            const int kc = ks + lt;
            uint32_t ah[2][4], al[2][4], bh[4][2], bl[4][2];
#pragma unroll
            for (int mt = 0; mt < 2; mt++) {
                int r = wm * 32 + mt * 16 + lg;
                float2 p0 = As[r][kc],     p1 = As[r + 8][kc];
                float2 p2 = As[r][kc + 4], p3 = As[r + 8][kc + 4];
                ah[mt][0] = __float_as_uint(p0.x); al[mt][0] = __float_as_uint(p0.y);
                ah[mt][1] = __float_as_uint(p1.x); al[mt][1] = __float_as_uint(p1.y);
                ah[mt][2] = __float_as_uint(p2.x); al[mt][2] = __float_as_uint(p2.y);
                ah[mt][3] = __float_as_uint(p3.x); al[mt][3] = __float_as_uint(p3.y);
            }
#pragma unroll
            for (int nt = 0; nt < 4; nt++) {
                int c = wn * 32 + nt * 8 + lg;
                float2 q0 = Bs[c][kc], q1 = Bs[c][kc + 4];
                bh[nt][0] = __float_as_uint(q0.x); bl[nt][0] = __float_as_uint(q0.y);
                bh[nt][1] = __float_as_uint(q1.x); bl[nt][1] = __float_as_uint(q1.y);
            }
#pragma unroll
            for (int mt = 0; mt < 2; mt++)
#pragma unroll
                for (int nt = 0; nt < 4; nt++) {
                    mma_tf32(acc[mt][nt], ah[mt], bh[nt]);
                    mma_tf32(acc[mt][nt], al[mt], bh[nt]);
                    mma_tf32(acc[mt][nt], ah[mt], bl[nt]);
                }
        }
        __syncthreads();
    }
#pragma unroll
    for (int mt = 0; mt < 2; mt++) {
        int r0 = bm + wm * 32 + mt * 16 + lg;
#pragma unroll
        for (int nt = 0; nt < 4; nt++) {
            int c0 = bn + wn * 32 + nt * 8 + lt * 2;
#pragma unroll
            for (int j = 0; j < 4; j++) {
                int row = r0 + (j >> 1) * 8;
                int col = c0 + (j & 1);
                if (row >= M) continue;
                float v = acc[mt][nt][j] + (bias ? bias[col] : 0.f);
                if (EP == EP_GATE) v = gateA[(size_t)row * K + col] * sigf(v);
                else if (EP == EP_RELU) v = fmaxf(v, 0.f);
                size_t idx = (size_t)row * N + col;
                if (WRITEC) C[idx] = v;
                if (SPLITOUT) {
                    float h, l; tf32_split(v, h, l);
                    Ch[idx] = h; Cl[idx] = l;
                }
            }
        }
    }
}

// ---------------- CSR build ----------------
__global__ void zero_kernel() {
    int i = blockIdx.x * blockDim.x + threadIdx.x;
    if (i < NN) { g_deg[i] = 0; g_cursor[i] = 0; g_easum[i] = 0.f; }
    if (i == 0) g_total = 0;
}
__global__ void deg_kernel(const int* __restrict__ dst, const float* __restrict__ ea) {
    int e = blockIdx.x * blockDim.x + threadIdx.x;
    if (e < NE) {
        int d = dst[e];
        atomicAdd(&g_deg[d], 1);
        atomicAdd(&g_easum[d], ea[e]);
    }
}
__global__ void loop_kernel() {
    int n = blockIdx.x * blockDim.x + threadIdx.x;
    if (n < NN) g_loop[n] = g_easum[n] / fmaxf((float)g_deg[n], 1.f);
}
__global__ void alloc_kernel() {
    __shared__ int s[1024];
    __shared__ int base;
    int tid = threadIdx.x;
    int i = blockIdx.x * 1024 + tid;
    int v = (i < NN) ? g_deg[i] : 0;
    s[tid] = v;
    __syncthreads();
    for (int off = 1; off < 1024; off <<= 1) {
        int t = (tid >= off) ? s[tid - off] : 0;
        __syncthreads();
        s[tid] += t;
        __syncthreads();
    }
    int incl = s[tid];
    if (tid == 1023) base = atomicAdd(&g_total, s[1023]);
    __syncthreads();
    if (i < NN) g_rowstart[i] = base + incl - v;
}
__global__ void csr_kernel(const int* __restrict__ dst) {
    int e = blockIdx.x * blockDim.x + threadIdx.x;
    if (e < NE) {
        int d = dst[e];
        int pos = atomicAdd(&g_cursor[d], 1);
        g_csr[g_rowstart[d] + pos] = e;
    }
}

// ---------------- attention coefficients ----------------
template <int H>
__global__ void attn_kernel(const float* __restrict__ hbuf, int stride,
                            const float* __restrict__ a_s, const float* __restrict__ a_d) {
    int w = (blockIdx.x * blockDim.x + threadIdx.x) >> 5;
    int lane = threadIdx.x & 31;
    if (w >= NN * H) return;
    int n = w / H, hh = w % H;
    const float* hr = hbuf + (size_t)n * stride + hh * 64;
    float as0 = a_s[hh * 64 + lane], as1 = a_s[hh * 64 + lane + 32];
    float ad0 = a_d[hh * 64 + lane], ad1 = a_d[hh * 64 + lane + 32];
    float h0 = hr[lane], h1 = hr[lane + 32];
    float vs = h0 * as0 + h1 * as1;
    float vd = h0 * ad0 + h1 * ad1;
#pragma unroll
    for (int off = 16; off > 0; off >>= 1) {
        vs += __shfl_down_sync(0xffffffffu, vs, off);
        vd += __shfl_down_sync(0xffffffffu, vd, off);
    }
    if (lane == 0) { g_asrc[w] = vs; g_adst[w] = vd; }
}

__global__ void ch_kernel(const float* __restrict__ We, const float* __restrict__ ae, int H, int C) {
    int h = threadIdx.x;
    if (h < H) {
        float s = 0.f;
        for (int c = 0; c < C; c++) s += We[h * C + c] * ae[h * C + c];
        g_ch[h] = s;
    }
}

// ---------------- per-node softmax aggregation ----------------
template <int H, int C, bool SPLIT, bool WRITEO>
__global__ void agg2(const float* __restrict__ hbuf, int hstride,
                     const int* __restrict__ src, const float* __restrict__ ea,
                     const float* __restrict__ bias,
                     const float* __restrict__ resid, int rstride,
                     float* __restrict__ out, float* __restrict__ outh,
                     float* __restrict__ outl) {
    constexpr int OUT = H * C;
    constexpr int CH = 64;
    __shared__ float s_m[H], s_z[H], s_adst[H], s_chh[H];
    __shared__ float s_alpha[CH * H];
    __shared__ int s_sid[CH];

    const int n = blockIdx.x;
    const int tid = threadIdx.x;
    const int deg = g_deg[n];
    const int rs = g_rowstart[n];
    const int T = deg + 1;
    const float loopv = g_loop[n];

    if (tid < H) { s_adst[tid] = g_adst[n * H + tid]; s_chh[tid] = g_ch[tid]; }

    if (tid < 32) {
        float m[H], zz[H], adst[H], chh[H];
#pragma unroll
        for (int h = 0; h < H; h++) {
            adst[h] = g_adst[n * H + h]; chh[h] = g_ch[h];
            m[h] = -1e30f; zz[h] = 0.f;
        }
        for (int i = tid; i < T; i += 32) {
            int sN; float eav;
            if (i < deg) { int e = g_csr[rs + i]; sN = src[e]; eav = ea[e]; }
            else { sN = n; eav = loopv; }
#pragma unroll
            for (int h = 0; h < H; h++) {
                float v = g_asrc[sN * H + h] + adst[h] + chh[h] * eav;
                v = (v >= 0.f) ? v : 0.2f * v;
                float nm = fmaxf(m[h], v);
                zz[h] = zz[h] * __expf(m[h] - nm) + __expf(v - nm);
                m[h] = nm;
            }
        }
#pragma unroll
        for (int off = 16; off > 0; off >>= 1) {
#pragma unroll
            for (int h = 0; h < H; h++) {
                float om = __shfl_xor_sync(0xffffffffu, m[h], off);
                float oz = __shfl_xor_sync(0xffffffffu, zz[h], off);
                float nm = fmaxf(m[h], om);
                zz[h] = zz[h] * __expf(m[h] - nm) + oz * __expf(om - nm);
                m[h] = nm;
            }
        }
        if (tid == 0) {
#pragma unroll
            for (int h = 0; h < H; h++) { s_m[h] = m[h]; s_z[h] = zz[h]; }
        }
    }
    __syncthreads();

    // gather pass: 4x unrolled for MLP
    const int hh = tid / C;
    float acc = 0.f;
    for (int base = 0; base < T; base += CH) {
        int i = base + tid;
        if (tid < CH && i < T) {
            int sN; float eav;
            if (i < deg) { int e = g_csr[rs + i]; sN = src[e]; eav = ea[e]; }
            else { sN = n; eav = loopv; }
#pragma unroll
            for (int h = 0; h < H; h++) {
                float v = g_asrc[sN * H + h] + s_adst[h] + s_chh[h] * eav;
                v = (v >= 0.f) ? v : 0.2f * v;
                s_alpha[tid * H + h] = __expf(v - s_m[h]) / s_z[h];
            }
            s_sid[tid] = sN;
        }
        __syncthreads();
        int lim = min(CH, T - base);
        float a0 = 0.f, a1 = 0.f, a2 = 0.f, a3 = 0.f;
        int j = 0;
        for (; j + 4 <= lim; j += 4) {
            a0 += s_alpha[(j + 0) * H + hh] * hbuf[(size_t)s_sid[j + 0] * hstride + tid];
            a1 += s_alpha[(j + 1) * H + hh] * hbuf[(size_t)s_sid[j + 1] * hstride + tid];
            a2 += s_alpha[(j + 2) * H + hh] * hbuf[(size_t)s_sid[j + 2] * hstride + tid];
            a3 += s_alpha[(j + 3) * H + hh] * hbuf[(size_t)s_sid[j + 3] * hstride + tid];
        }
        for (; j < lim; j++)
            a0 += s_alpha[j * H + hh] * hbuf[(size_t)s_sid[j] * hstride + tid];
        acc += (a0 + a1) + (a2 + a3);
        __syncthreads();
    }
    float v = acc + bias[tid];
    v = (v >= 0.f) ? v : 0.01f * v;
    v += resid[(size_t)n * rstride + tid];
    size_t idx = (size_t)n * OUT + tid;
    if (WRITEO) out[idx] = v;
    if (SPLIT) {
        float h, l; tf32_split(v, h, l);
        outh[idx] = h; outl[idx] = l;
    }
}

// ---------------- driver ----------------
extern "C" void kernel_launch(void* const* d_in, const int* in_sizes, int n_in,
                              void* d_out, int out_size) {
    const float* x     = (const float*)d_in[0];
    const int*   eidx  = (const int*)d_in[1];
    const float* ea    = (const float*)d_in[2];
    const float* fa_w  = (const float*)d_in[3];
    const float* fa_b  = (const float*)d_in[4];
    const float* W1    = (const float*)d_in[5];
    const float* We1   = (const float*)d_in[6];
    const float* as1   = (const float*)d_in[7];
    const float* ad1   = (const float*)d_in[8];
    const float* ae1   = (const float*)d_in[9];
    const float* b1    = (const float*)d_in[10];
    const float* W2    = (const float*)d_in[11];
    const float* We2   = (const float*)d_in[12];
    const float* as2   = (const float*)d_in[13];
    const float* ad2   = (const float*)d_in[14];
    const float* ae2   = (const float*)d_in[15];
    const float* b2    = (const float*)d_in[16];
    const float* W3    = (const float*)d_in[17];
    const float* We3   = (const float*)d_in[18];
    const float* as3   = (const float*)d_in[19];
    const float* ad3   = (const float*)d_in[20];
    const float* ae3   = (const float*)d_in[21];
    const float* b3    = (const float*)d_in[22];
    const float* r1_w  = (const float*)d_in[23];
    const float* r1_b  = (const float*)d_in[24];
    const float* r2_w  = (const float*)d_in[25];
    const float* r2_b  = (const float*)d_in[26];
    const float* ffn_w1 = (const float*)d_in[27];
    const float* ffn_b1 = (const float*)d_in[28];
    const float* ffn_w2 = (const float*)d_in[29];
    const float* ffn_b2 = (const float*)d_in[30];
    float* out = (float*)d_out;

    const int* src = eidx;
    const int* dst = eidx + NE;

    float *xh, *xl, *gxh, *gxl, *hr, *z1h, *z1l, *z2h, *z2l;
    float *t64h, *t64l, *zself, *h3;
    float *wfah, *wfal, *wb1h, *wb1l, *wb2h, *wb2l, *w3h, *w3l, *wf1h, *wf1l, *wf2h, *wf2l;
    cudaGetSymbolAddress((void**)&xh, g_xh);   cudaGetSymbolAddress((void**)&xl, g_xl);
    cudaGetSymbolAddress((void**)&gxh, g_gxh); cudaGetSymbolAddress((void**)&gxl, g_gxl);
    cudaGetSymbolAddress((void**)&hr, g_hr);
    cudaGetSymbolAddress((void**)&z1h, g_z1h); cudaGetSymbolAddress((void**)&z1l, g_z1l);
    cudaGetSymbolAddress((void**)&z2h, g_z2h); cudaGetSymbolAddress((void**)&z2l, g_z2l);
    cudaGetSymbolAddress((void**)&t64h, g_t64h); cudaGetSymbolAddress((void**)&t64l, g_t64l);
    cudaGetSymbolAddress((void**)&zself, g_zself);
    cudaGetSymbolAddress((void**)&h3, g_h3);
    cudaGetSymbolAddress((void**)&wfah, g_wfa_h); cudaGetSymbolAddress((void**)&wfal, g_wfa_l);
    cudaGetSymbolAddress((void**)&wb1h, g_wb1_h); cudaGetSymbolAddress((void**)&wb1l, g_wb1_l);
    cudaGetSymbolAddress((void**)&wb2h, g_wb2_h); cudaGetSymbolAddress((void**)&wb2l, g_wb2_l);
    cudaGetSymbolAddress((void**)&w3h, g_w3_h);   cudaGetSymbolAddress((void**)&w3l, g_w3_l);
    cudaGetSymbolAddress((void**)&wf1h, g_wf1_h); cudaGetSymbolAddress((void**)&wf1l, g_wf1_l);
    cudaGetSymbolAddress((void**)&wf2h, g_wf2_h); cudaGetSymbolAddress((void**)&wf2l, g_wf2_l);
    float *bb1, *bb2;
    cudaGetSymbolAddress((void**)&bb1, g_bb1);
    cudaGetSymbolAddress((void**)&bb2, g_bb2);

    const int TB = 256;
    const int nbN = (NN + TB - 1) / TB;
    const int nbE = (NE + TB - 1) / TB;

    // CSR build
    zero_kernel<<<nbN, TB>>>();
    deg_kernel<<<nbE, TB>>>(dst, ea);
    loop_kernel<<<nbN, TB>>>();
    alloc_kernel<<<(NN + 1023) / 1024, 1024>>>();
    csr_kernel<<<nbE, TB>>>(dst);

    // weight pre-splits
    split_kernel<<<(128 * 128 + 255) / 256, 256>>>(fa_w, wfah, wfal, 128 * 128);
    fusepack_kernel<<<(128 * 512 + 255) / 256, 256>>>(r1_w, W1, wb1h, wb1l, 128, 256);
    fusepack_kernel<<<(256 * 512 + 255) / 256, 256>>>(r2_w, W2, wb2h, wb2l, 256, 256);
    split_kernel<<<(256 * 64 + 255) / 256, 256>>>(W3, w3h, w3l, 256 * 64);
    split_kernel<<<(128 * 64 + 255) / 256, 256>>>(ffn_w1, wf1h, wf1l, 128 * 64);
    split_kernel<<<(64 * 64 + 255) / 256, 256>>>(ffn_w2, wf2h, wf2l, 64 * 64);
    biaspack_kernel<<<2, 256>>>(r1_b, r2_b);

    split_kernel<<<(NN * 128 + 255) / 256, 256>>>(x, xh, xl, NN * 128);

    {   // gate: splits of gx only
        dim3 g(128 / 64, (NN + 127) / 128);
        gemm3<EP_GATE, true, false><<<g, 256>>>(xh, xl, wfah, wfal, fa_b, x,
                                                nullptr, gxh, gxl, NN, 128, 128);
    }
    {   // ffn1: relu, splits only
        dim3 g(64 / 64, (NN + 127) / 128);
        gemm3<EP_RELU, true, false><<<g, 256>>>(gxh, gxl, wf1h, wf1l, ffn_b1, nullptr,
                                                nullptr, t64h, t64l, NN, 128, 64);
    }
    {   // ffn2: fp32 zself
        dim3 g(64 / 64, (NN + 127) / 128);
        gemm3<EP_NONE, false, true><<<g, 256>>>(t64h, t64l, wf2h, wf2l, ffn_b2, nullptr,
                                                zself, nullptr, nullptr, NN, 64, 64);
    }

    // --- layer 1 ---
    {
        dim3 g(512 / 64, (NN + 127) / 128);
        gemm3<EP_NONE, false, true><<<g, 256>>>(gxh, gxl, wb1h, wb1l, bb1, nullptr,
                                                hr, nullptr, nullptr, NN, 128, 512);
    }
    attn_kernel<4><<<(NN * 4 * 32 + TB - 1) / TB, TB>>>(hr + 256, 512, as1, ad1);
    ch_kernel<<<1, 4>>>(We1, ae1, 4, 64);
    agg2<4, 64, true, false><<<NN, 256>>>(hr + 256, 512, src, ea, b1, hr, 512,
                                          nullptr, z1h, z1l);

    // --- layer 2 ---
    {
        dim3 g(512 / 64, (NN + 127) / 128);
        gemm3<EP_NONE, false, true><<<g, 256>>>(z1h, z1l, wb2h, wb2l, bb2, nullptr,
                                                hr, nullptr, nullptr, NN, 256, 512);
    }
    attn_kernel<4><<<(NN * 4 * 32 + TB - 1) / TB, TB>>>(hr + 256, 512, as2, ad2);
    ch_kernel<<<1, 4>>>(We2, ae2, 4, 64);
    agg2<4, 64, true, false><<<NN, 256>>>(hr + 256, 512, src, ea, b2, hr, 512,
                                          nullptr, z2h, z2l);

    // --- layer 3 ---
    {
        dim3 g(64 / 64, (NN + 127) / 128);
        gemm3<EP_NONE, false, true><<<g, 256>>>(z2h, z2l, w3h, w3l, nullptr, nullptr,
                                                h3, nullptr, nullptr, NN, 256, 64);
    }
    attn_kernel<1><<<(NN * 32 + TB - 1) / TB, TB>>>(h3, 64, as3, ad3);
    ch_kernel<<<1, 1>>>(We3, ae3, 1, 64);
    agg2<1, 64, false, true><<<NN, 64>>>(h3, 64, src, ea, b3, zself, 64,
                                         out, nullptr, nullptr);
}

// round 5
// speedup vs baseline: 1.0760x; 1.0760x over previous
#include <cuda_runtime.h>
#include <cuda_bf16.h>
#include <math.h>
#include <stdint.h>

#define NN 50000
#define NE 800000

// ---------------- scratch (device globals) ----------------
__device__ float g_xh[NN * 128], g_xl[NN * 128];
__device__ float g_gxh[NN * 128], g_gxl[NN * 128];
__device__ float g_hr[NN * 512];                           // [res | h] fused layer out
__device__ float g_z1h[NN * 256], g_z1l[NN * 256];
__device__ float g_z2h[NN * 256], g_z2l[NN * 256];
__device__ float g_t64h[NN * 64], g_t64l[NN * 64];
__device__ float g_zself[NN * 64];
__device__ float g_h3[NN * 64];
__device__ float g_asrc[NN * 4];
__device__ float g_adst[NN * 4];
__device__ float g_loop[NN];
__device__ float g_easum[NN];
__device__ int   g_deg[NN];
__device__ int   g_rowstart[NN];
__device__ int   g_cursor[NN];
__device__ int   g_csr[NE];
__device__ float g_ch[4];
__device__ int   g_total;
__device__ float g_wfa_h[128 * 128], g_wfa_l[128 * 128];
__device__ float g_wb1_h[128 * 512], g_wb1_l[128 * 512];
__device__ float g_wb2_h[256 * 512], g_wb2_l[256 * 512];
__device__ float g_w3_h[256 * 64],  g_w3_l[256 * 64];
__device__ float g_wf1_h[128 * 64], g_wf1_l[128 * 64];
__device__ float g_wf2_h[64 * 64],  g_wf2_l[64 * 64];
__device__ float g_bb1[512], g_bb2[512];

__device__ __forceinline__ float sigf(float x) { return 1.f / (1.f + __expf(-x)); }

__device__ __forceinline__ void tf32_split(float x, float& hi, float& lo) {
    uint32_t uh;
    asm("cvt.rna.tf32.f32 %0, %1;" : "=r"(uh) : "f"(x));
    hi = __uint_as_float(uh);
    float r = x - hi;
    uint32_t ul;
    asm("cvt.rna.tf32.f32 %0, %1;" : "=r"(ul) : "f"(r));
    lo = __uint_as_float(ul);
}

__device__ __forceinline__ void mma_tf32(float* c, const uint32_t* a, const uint32_t* b) {
    asm volatile(
        "mma.sync.aligned.m16n8k8.row.col.f32.tf32.tf32.f32 "
        "{%0,%1,%2,%3}, {%4,%5,%6,%7}, {%8,%9}, {%0,%1,%2,%3};\n"
        : "+f"(c[0]), "+f"(c[1]), "+f"(c[2]), "+f"(c[3])
        : "r"(a[0]), "r"(a[1]), "r"(a[2]), "r"(a[3]), "r"(b[0]), "r"(b[1]));
}

// ---------------- pack / split kernels ----------------
__global__ void split_kernel(const float* __restrict__ s, float* __restrict__ dh,
                             float* __restrict__ dl, int n) {
    int i = blockIdx.x * blockDim.x + threadIdx.x;
    if (i < n) { float h, l; tf32_split(s[i], h, l); dh[i] = h; dl[i] = l; }
}
__global__ void fusepack_kernel(const float* __restrict__ A, const float* __restrict__ B,
                                float* __restrict__ dh, float* __restrict__ dl,
                                int rows, int half) {
    int i = blockIdx.x * blockDim.x + threadIdx.x;
    int tot = rows * 2 * half;
    if (i < tot) {
        int r = i / (2 * half), c = i % (2 * half);
        float v = (c < half) ? A[r * half + c] : B[r * half + c - half];
        float h, l; tf32_split(v, h, l); dh[i] = h; dl[i] = l;
    }
}
__global__ void biaspack_kernel(const float* __restrict__ r1b, const float* __restrict__ r2b) {
    int i = blockIdx.x * blockDim.x + threadIdx.x;
    if (i < 512) {
        g_bb1[i] = (i < 256) ? r1b[i] : 0.f;
        g_bb2[i] = (i < 256) ? r2b[i] : 0.f;
    }
}

#define EP_NONE 0
#define EP_GATE 1
#define EP_RELU 2

// ---------------- gemm2: R3-proven kernel, BM=128 BN=64 (used for N=64) ----
template <int EP, bool SPLITOUT, bool WRITEC>
__global__ __launch_bounds__(256) void gemm2(
    const float* __restrict__ Agh, const float* __restrict__ Agl,
    const float* __restrict__ Bgh, const float* __restrict__ Bgl,
    const float* __restrict__ bias, const float* __restrict__ gateA,
    float* __restrict__ C, float* __restrict__ Ch, float* __restrict__ Cl,
    int M, int K, int N) {
    __shared__ float Ash[128][20], Asl[128][20];
    __shared__ float Bsh[64][20],  Bsl[64][20];
    const int bm = blockIdx.y * 128, bn = blockIdx.x * 64;
    const int tid = threadIdx.x, lane = tid & 31, wid = tid >> 5;
    const int wm = wid >> 1, wn = wid & 1;
    const int lg = lane >> 2, lt = lane & 3;
    const int ar0 = tid >> 2, as0 = (tid & 3) * 4;
    const int bkk = tid >> 4, bn4 = (tid & 15) * 4;

    float acc[2][4][4];
#pragma unroll
    for (int mt = 0; mt < 2; mt++)
#pragma unroll
        for (int nt = 0; nt < 4; nt++)
#pragma unroll
            for (int j = 0; j < 4; j++) acc[mt][nt][j] = 0.f;

    float4 rah[2], ral[2], rbh, rbl;
    const float4 z4 = make_float4(0.f, 0.f, 0.f, 0.f);

#pragma unroll
    for (int t = 0; t < 2; t++) {
        int r = ar0 + t * 64;
        if (bm + r < M) {
            rah[t] = *(const float4*)&Agh[(size_t)(bm + r) * K + as0];
            ral[t] = *(const float4*)&Agl[(size_t)(bm + r) * K + as0];
        } else { rah[t] = z4; ral[t] = z4; }
    }
    rbh = *(const float4*)&Bgh[(size_t)bkk * N + bn + bn4];
    rbl = *(const float4*)&Bgl[(size_t)bkk * N + bn + bn4];

    for (int k0 = 0; k0 < K; k0 += 16) {
#pragma unroll
        for (int t = 0; t < 2; t++) {
            int r = ar0 + t * 64;
            Ash[r][as0 + 0] = rah[t].x; Ash[r][as0 + 1] = rah[t].y;
            Ash[r][as0 + 2] = rah[t].z; Ash[r][as0 + 3] = rah[t].w;
            Asl[r][as0 + 0] = ral[t].x; Asl[r][as0 + 1] = ral[t].y;
            Asl[r][as0 + 2] = ral[t].z; Asl[r][as0 + 3] = ral[t].w;
        }
        Bsh[bn4 + 0][bkk] = rbh.x; Bsh[bn4 + 1][bkk] = rbh.y;
        Bsh[bn4 + 2][bkk] = rbh.z; Bsh[bn4 + 3][bkk] = rbh.w;
        Bsl[bn4 + 0][bkk] = rbl.x; Bsl[bn4 + 1][bkk] = rbl.y;
        Bsl[bn4 + 2][bkk] = rbl.z; Bsl[bn4 + 3][bkk] = rbl.w;
        __syncthreads();
        if (k0 + 16 < K) {
            int kn = k0 + 16;
#pragma unroll
            for (int t = 0; t < 2; t++) {
                int r = ar0 + t * 64;
                if (bm + r < M) {
                    rah[t] = *(const float4*)&Agh[(size_t)(bm + r) * K + kn + as0];
                    ral[t] = *(const float4*)&Agl[(size_t)(bm + r) * K + kn + as0];
                } else { rah[t] = z4; ral[t] = z4; }
            }
            rbh = *(const float4*)&Bgh[(size_t)(kn + bkk) * N + bn + bn4];
            rbl = *(const float4*)&Bgl[(size_t)(kn + bkk) * N + bn + bn4];
        }
#pragma unroll
        for (int ks = 0; ks < 16; ks += 8) {
            const int kc = ks + lt;
            uint32_t ah[2][4], al[2][4], bh[4][2], bl[4][2];
#pragma unroll
            for (int mt = 0; mt < 2; mt++) {
                int r = wm * 32 + mt * 16 + lg;
                ah[mt][0] = __float_as_uint(Ash[r][kc]);
                ah[mt][1] = __float_as_uint(Ash[r + 8][kc]);
                ah[mt][2] = __float_as_uint(Ash[r][kc + 4]);
                ah[mt][3] = __float_as_uint(Ash[r + 8][kc + 4]);
                al[mt][0] = __float_as_uint(Asl[r][kc]);
                al[mt][1] = __float_as_uint(Asl[r + 8][kc]);
                al[mt][2] = __float_as_uint(Asl[r][kc + 4]);
                al[mt][3] = __float_as_uint(Asl[r + 8][kc + 4]);
            }
#pragma unroll
            for (int nt = 0; nt < 4; nt++) {
                int c = wn * 32 + nt * 8 + lg;
                bh[nt][0] = __float_as_uint(Bsh[c][kc]);
                bh[nt][1] = __float_as_uint(Bsh[c][kc + 4]);
                bl[nt][0] = __float_as_uint(Bsl[c][kc]);
                bl[nt][1] = __float_as_uint(Bsl[c][kc + 4]);
            }
#pragma unroll
            for (int mt = 0; mt < 2; mt++)
#pragma unroll
                for (int nt = 0; nt < 4; nt++) {
                    mma_tf32(acc[mt][nt], ah[mt], bh[nt]);
                    mma_tf32(acc[mt][nt], al[mt], bh[nt]);
                    mma_tf32(acc[mt][nt], ah[mt], bl[nt]);
                }
        }
        __syncthreads();
    }
#pragma unroll
    for (int mt = 0; mt < 2; mt++) {
        int r0 = bm + wm * 32 + mt * 16 + lg;
#pragma unroll
        for (int nt = 0; nt < 4; nt++) {
            int c0 = bn + wn * 32 + nt * 8 + lt * 2;
#pragma unroll
            for (int j = 0; j < 4; j++) {
                int row = r0 + (j >> 1) * 8;
                int col = c0 + (j & 1);
                if (row >= M) continue;
                float v = acc[mt][nt][j] + (bias ? bias[col] : 0.f);
                if (EP == EP_GATE) v = gateA[(size_t)row * K + col] * sigf(v);
                else if (EP == EP_RELU) v = fmaxf(v, 0.f);
                size_t idx = (size_t)row * N + col;
                if (WRITEC) C[idx] = v;
                if (SPLITOUT) {
                    float h, l; tf32_split(v, h, l);
                    Ch[idx] = h; Cl[idx] = l;
                }
            }
        }
    }
}

// ---------------- gemm4: BM=128 BN=128, warp tile 32x64 (N % 128 == 0) ------
template <int EP, bool SPLITOUT, bool WRITEC>
__global__ __launch_bounds__(256, 1) void gemm4(
    const float* __restrict__ Agh, const float* __restrict__ Agl,
    const float* __restrict__ Bgh, const float* __restrict__ Bgl,
    const float* __restrict__ bias, const float* __restrict__ gateA,
    float* __restrict__ C, float* __restrict__ Ch, float* __restrict__ Cl,
    int M, int K, int N) {
    __shared__ float Ash[128][20], Asl[128][20];
    __shared__ float Bsh[128][20], Bsl[128][20];
    const int bm = blockIdx.y * 128, bn = blockIdx.x * 128;
    const int tid = threadIdx.x, lane = tid & 31, wid = tid >> 5;
    const int wm = wid >> 1, wn = wid & 1;    // 4 x 2 warps; warp tile 32 x 64
    const int lg = lane >> 2, lt = lane & 3;
    const int ar0 = tid >> 2, as0 = (tid & 3) * 4;   // A: 128x16, 2 float4/thread
    const int bkk = tid >> 5, bn4 = (tid & 31) * 4;  // B: 16x128, 2 float4/thread

    float acc[2][8][4];
#pragma unroll
    for (int mt = 0; mt < 2; mt++)
#pragma unroll
        for (int nt = 0; nt < 8; nt++)
#pragma unroll
            for (int j = 0; j < 4; j++) acc[mt][nt][j] = 0.f;

    float4 rah[2], ral[2], rbh[2], rbl[2];
    const float4 z4 = make_float4(0.f, 0.f, 0.f, 0.f);

#pragma unroll
    for (int t = 0; t < 2; t++) {
        int r = ar0 + t * 64;
        if (bm + r < M) {
            rah[t] = *(const float4*)&Agh[(size_t)(bm + r) * K + as0];
            ral[t] = *(const float4*)&Agl[(size_t)(bm + r) * K + as0];
        } else { rah[t] = z4; ral[t] = z4; }
        int kk = bkk + t * 8;
        rbh[t] = *(const float4*)&Bgh[(size_t)kk * N + bn + bn4];
        rbl[t] = *(const float4*)&Bgl[(size_t)kk * N + bn + bn4];
    }

    for (int k0 = 0; k0 < K; k0 += 16) {
#pragma unroll
        for (int t = 0; t < 2; t++) {
            int r = ar0 + t * 64;
            Ash[r][as0 + 0] = rah[t].x; Ash[r][as0 + 1] = rah[t].y;
            Ash[r][as0 + 2] = rah[t].z; Ash[r][as0 + 3] = rah[t].w;
            Asl[r][as0 + 0] = ral[t].x; Asl[r][as0 + 1] = ral[t].y;
            Asl[r][as0 + 2] = ral[t].z; Asl[r][as0 + 3] = ral[t].w;
            int kk = bkk + t * 8;
            Bsh[bn4 + 0][kk] = rbh[t].x; Bsh[bn4 + 1][kk] = rbh[t].y;
            Bsh[bn4 + 2][kk] = rbh[t].z; Bsh[bn4 + 3][kk] = rbh[t].w;
            Bsl[bn4 + 0][kk] = rbl[t].x; Bsl[bn4 + 1][kk] = rbl[t].y;
            Bsl[bn4 + 2][kk] = rbl[t].z; Bsl[bn4 + 3][kk] = rbl[t].w;
        }
        __syncthreads();
        if (k0 + 16 < K) {
            int kn = k0 + 16;
#pragma unroll
            for (int t = 0; t < 2; t++) {
                int r = ar0 + t * 64;
                if (bm + r < M) {
                    rah[t] = *(const float4*)&Agh[(size_t)(bm + r) * K + kn + as0];
                    ral[t] = *(const float4*)&Agl[(size_t)(bm + r) * K + kn + as0];
                } else { rah[t] = z4; ral[t] = z4; }
                int kk = bkk + t * 8;
                rbh[t] = *(const float4*)&Bgh[(size_t)(kn + kk) * N + bn + bn4];
                rbl[t] = *(const float4*)&Bgl[(size_t)(kn + kk) * N + bn + bn4];
            }
        }
#pragma unroll
        for (int ks = 0; ks < 16; ks += 8) {
            const int kc = ks + lt;
            uint32_t ah[2][4], al[2][4];
#pragma unroll
            for (int mt = 0; mt < 2; mt++) {
                int r = wm * 32 + mt * 16 + lg;
                ah[mt][0] = __float_as_uint(Ash[r][kc]);
                ah[mt][1] = __float_as_uint(Ash[r + 8][kc]);
                ah[mt][2] = __float_as_uint(Ash[r][kc + 4]);
                ah[mt][3] = __float_as_uint(Ash[r + 8][kc + 4]);
                al[mt][0] = __float_as_uint(Asl[r][kc]);
                al[mt][1] = __float_as_uint(Asl[r + 8][kc]);
                al[mt][2] = __float_as_uint(Asl[r][kc + 4]);
                al[mt][3] = __float_as_uint(Asl[r + 8][kc + 4]);
            }
#pragma unroll
            for (int nt = 0; nt < 8; nt++) {
                int c = wn * 64 + nt * 8 + lg;
                uint32_t bh[2], bl[2];
                bh[0] = __float_as_uint(Bsh[c][kc]);
                bh[1] = __float_as_uint(Bsh[c][kc + 4]);
                bl[0] = __float_as_uint(Bsl[c][kc]);
                bl[1] = __float_as_uint(Bsl[c][kc + 4]);
#pragma unroll
                for (int mt = 0; mt < 2; mt++) {
                    mma_tf32(acc[mt][nt], ah[mt], bh);
                    mma_tf32(acc[mt][nt], al[mt], bh);
                    mma_tf32(acc[mt][nt], ah[mt], bl);
                }
            }
        }
        __syncthreads();
    }
#pragma unroll
    for (int mt = 0; mt < 2; mt++) {
        int r0 = bm + wm * 32 + mt * 16 + lg;
#pragma unroll
        for (int nt = 0; nt < 8; nt++) {
            int c0 = bn + wn * 64 + nt * 8 + lt * 2;
#pragma unroll
            for (int j = 0; j < 4; j++) {
                int row = r0 + (j >> 1) * 8;
                int col = c0 + (j & 1);
                if (row >= M) continue;
                float v = acc[mt][nt][j] + (bias ? bias[col] : 0.f);
                if (EP == EP_GATE) v = gateA[(size_t)row * K + col] * sigf(v);
                else if (EP == EP_RELU) v = fmaxf(v, 0.f);
                size_t idx = (size_t)row * N + col;
                if (WRITEC) C[idx] = v;
                if (SPLITOUT) {
                    float h, l; tf32_split(v, h, l);
                    Ch[idx] = h; Cl[idx] = l;
                }
            }
        }
    }
}

// ---------------- CSR build ----------------
__global__ void zero_kernel() {
    int i = blockIdx.x * blockDim.x + threadIdx.x;
    if (i < NN) { g_deg[i] = 0; g_cursor[i] = 0; g_easum[i] = 0.f; }
    if (i == 0) g_total = 0;
}
__global__ void deg_kernel(const int* __restrict__ dst, const float* __restrict__ ea) {
    int e = blockIdx.x * blockDim.x + threadIdx.x;
    if (e < NE) {
        int d = dst[e];
        atomicAdd(&g_deg[d], 1);
        atomicAdd(&g_easum[d], ea[e]);
    }
}
__global__ void loop_kernel() {
    int n = blockIdx.x * blockDim.x + threadIdx.x;
    if (n < NN) g_loop[n] = g_easum[n] / fmaxf((float)g_deg[n], 1.f);
}
__global__ void alloc_kernel() {
    __shared__ int s[1024];
    __shared__ int base;
    int tid = threadIdx.x;
    int i = blockIdx.x * 1024 + tid;
    int v = (i < NN) ? g_deg[i] : 0;
    s[tid] = v;
    __syncthreads();
    for (int off = 1; off < 1024; off <<= 1) {
        int t = (tid >= off) ? s[tid - off] : 0;
        __syncthreads();
        s[tid] += t;
        __syncthreads();
    }
    int incl = s[tid];
    if (tid == 1023) base = atomicAdd(&g_total, s[1023]);
    __syncthreads();
    if (i < NN) g_rowstart[i] = base + incl - v;
}
__global__ void csr_kernel(const int* __restrict__ dst) {
    int e = blockIdx.x * blockDim.x + threadIdx.x;
    if (e < NE) {
        int d = dst[e];
        int pos = atomicAdd(&g_cursor[d], 1);
        g_csr[g_rowstart[d] + pos] = e;
    }
}

// ---------------- attention coefficients ----------------
template <int H>
__global__ void attn_kernel(const float* __restrict__ hbuf, int stride,
                            const float* __restrict__ a_s, const float* __restrict__ a_d) {
    int w = (blockIdx.x * blockDim.x + threadIdx.x) >> 5;
    int lane = threadIdx.x & 31;
    if (w >= NN * H) return;
    int n = w / H, hh = w % H;
    const float* hr = hbuf + (size_t)n * stride + hh * 64;
    float as0 = a_s[hh * 64 + lane], as1 = a_s[hh * 64 + lane + 32];
    float ad0 = a_d[hh * 64 + lane], ad1 = a_d[hh * 64 + lane + 32];
    float h0 = hr[lane], h1 = hr[lane + 32];
    float vs = h0 * as0 + h1 * as1;
    float vd = h0 * ad0 + h1 * ad1;
#pragma unroll
    for (int off = 16; off > 0; off >>= 1) {
        vs += __shfl_down_sync(0xffffffffu, vs, off);
        vd += __shfl_down_sync(0xffffffffu, vd, off);
    }
    if (lane == 0) { g_asrc[w] = vs; g_adst[w] = vd; }
}

__global__ void ch_kernel(const float* __restrict__ We, const float* __restrict__ ae, int H, int C) {
    int h = threadIdx.x;
    if (h < H) {
        float s = 0.f;
        for (int c = 0; c < C; c++) s += We[h * C + c] * ae[h * C + c];
        g_ch[h] = s;
    }
}

// ---------------- per-node softmax aggregation ----------------
template <int H, int C, bool SPLIT, bool WRITEO>
__global__ void agg2(const float* __restrict__ hbuf, int hstride,
                     const int* __restrict__ src, const float* __restrict__ ea,
                     const float* __restrict__ bias,
                     const float* __restrict__ resid, int rstride,
                     float* __restrict__ out, float* __restrict__ outh,
                     float* __restrict__ outl) {
    constexpr int OUT = H * C;
    constexpr int CH = 64;
    __shared__ float s_m[H], s_z[H], s_adst[H], s_chh[H];
    __shared__ float s_alpha[CH * H];
    __shared__ int s_sid[CH];

    const int n = blockIdx.x;
    const int tid = threadIdx.x;
    const int deg = g_deg[n];
    const int rs = g_rowstart[n];
    const int T = deg + 1;
    const float loopv = g_loop[n];

    if (tid < H) { s_adst[tid] = g_adst[n * H + tid]; s_chh[tid] = g_ch[tid]; }

    if (tid < 32) {
        float m[H], zz[H], adst[H], chh[H];
#pragma unroll
        for (int h = 0; h < H; h++) {
            adst[h] = g_adst[n * H + h]; chh[h] = g_ch[h];
            m[h] = -1e30f; zz[h] = 0.f;
        }
        for (int i = tid; i < T; i += 32) {
            int sN; float eav;
            if (i < deg) { int e = g_csr[rs + i]; sN = src[e]; eav = ea[e]; }
            else { sN = n; eav = loopv; }
#pragma unroll
            for (int h = 0; h < H; h++) {
                float v = g_asrc[sN * H + h] + adst[h] + chh[h] * eav;
                v = (v >= 0.f) ? v : 0.2f * v;
                float nm = fmaxf(m[h], v);
                zz[h] = zz[h] * __expf(m[h] - nm) + __expf(v - nm);
                m[h] = nm;
            }
        }
#pragma unroll
        for (int off = 16; off > 0; off >>= 1) {
#pragma unroll
            for (int h = 0; h < H; h++) {
                float om = __shfl_xor_sync(0xffffffffu, m[h], off);
                float oz = __shfl_xor_sync(0xffffffffu, zz[h], off);
                float nm = fmaxf(m[h], om);
                zz[h] = zz[h] * __expf(m[h] - nm) + oz * __expf(om - nm);
                m[h] = nm;
            }
        }
        if (tid == 0) {
#pragma unroll
            for (int h = 0; h < H; h++) { s_m[h] = m[h]; s_z[h] = zz[h]; }
        }
    }
    __syncthreads();

    // gather pass (R3 loop)
    const int hh = tid / C;
    float acc = 0.f;
    for (int base = 0; base < T; base += CH) {
        int i = base + tid;
        if (tid < CH && i < T) {
            int sN; float eav;
            if (i < deg) { int e = g_csr[rs + i]; sN = src[e]; eav = ea[e]; }
            else { sN = n; eav = loopv; }
#pragma unroll
            for (int h = 0; h < H; h++) {
                float v = g_asrc[sN * H + h] + s_adst[h] + s_chh[h] * eav;
                v = (v >= 0.f) ? v : 0.2f * v;
                s_alpha[tid * H + h] = __expf(v - s_m[h]) / s_z[h];
            }
            s_sid[tid] = sN;
        }
        __syncthreads();
        int lim = min(CH, T - base);
        for (int j = 0; j < lim; j++)
            acc += s_alpha[j * H + hh] * hbuf[(size_t)s_sid[j] * hstride + tid];
        __syncthreads();
    }
    float v = acc + bias[tid];
    v = (v >= 0.f) ? v : 0.01f * v;
    v += resid[(size_t)n * rstride + tid];
    size_t idx = (size_t)n * OUT + tid;
    if (WRITEO) out[idx] = v;
    if (SPLIT) {
        float h, l; tf32_split(v, h, l);
        outh[idx] = h; outl[idx] = l;
    }
}

// ---------------- driver ----------------
extern "C" void kernel_launch(void* const* d_in, const int* in_sizes, int n_in,
                              void* d_out, int out_size) {
    const float* x     = (const float*)d_in[0];
    const int*   eidx  = (const int*)d_in[1];
    const float* ea    = (const float*)d_in[2];
    const float* fa_w  = (const float*)d_in[3];
    const float* fa_b  = (const float*)d_in[4];
    const float* W1    = (const float*)d_in[5];
    const float* We1   = (const float*)d_in[6];
    const float* as1   = (const float*)d_in[7];
    const float* ad1   = (const float*)d_in[8];
    const float* ae1   = (const float*)d_in[9];
    const float* b1    = (const float*)d_in[10];
    const float* W2    = (const float*)d_in[11];
    const float* We2   = (const float*)d_in[12];
    const float* as2   = (const float*)d_in[13];
    const float* ad2   = (const float*)d_in[14];
    const float* ae2   = (const float*)d_in[15];
    const float* b2    = (const float*)d_in[16];
    const float* W3    = (const float*)d_in[17];
    const float* We3   = (const float*)d_in[18];
    const float* as3   = (const float*)d_in[19];
    const float* ad3   = (const float*)d_in[20];
    const float* ae3   = (const float*)d_in[21];
    const float* b3    = (const float*)d_in[22];
    const float* r1_w  = (const float*)d_in[23];
    const float* r1_b  = (const float*)d_in[24];
    const float* r2_w  = (const float*)d_in[25];
    const float* r2_b  = (const float*)d_in[26];
    const float* ffn_w1 = (const float*)d_in[27];
    const float* ffn_b1 = (const float*)d_in[28];
    const float* ffn_w2 = (const float*)d_in[29];
    const float* ffn_b2 = (const float*)d_in[30];
    float* out = (float*)d_out;

    const int* src = eidx;
    const int* dst = eidx + NE;

    float *xh, *xl, *gxh, *gxl, *hr, *z1h, *z1l, *z2h, *z2l;
    float *t64h, *t64l, *zself, *h3;
    float *wfah, *wfal, *wb1h, *wb1l, *wb2h, *wb2l, *w3h, *w3l, *wf1h, *wf1l, *wf2h, *wf2l;
    cudaGetSymbolAddress((void**)&xh, g_xh);   cudaGetSymbolAddress((void**)&xl, g_xl);
    cudaGetSymbolAddress((void**)&gxh, g_gxh); cudaGetSymbolAddress((void**)&gxl, g_gxl);
    cudaGetSymbolAddress((void**)&hr, g_hr);
    cudaGetSymbolAddress((void**)&z1h, g_z1h); cudaGetSymbolAddress((void**)&z1l, g_z1l);
    cudaGetSymbolAddress((void**)&z2h, g_z2h); cudaGetSymbolAddress((void**)&z2l, g_z2l);
    cudaGetSymbolAddress((void**)&t64h, g_t64h); cudaGetSymbolAddress((void**)&t64l, g_t64l);
    cudaGetSymbolAddress((void**)&zself, g_zself);
    cudaGetSymbolAddress((void**)&h3, g_h3);
    cudaGetSymbolAddress((void**)&wfah, g_wfa_h); cudaGetSymbolAddress((void**)&wfal, g_wfa_l);
    cudaGetSymbolAddress((void**)&wb1h, g_wb1_h); cudaGetSymbolAddress((void**)&wb1l, g_wb1_l);
    cudaGetSymbolAddress((void**)&wb2h, g_wb2_h); cudaGetSymbolAddress((void**)&wb2l, g_wb2_l);
    cudaGetSymbolAddress((void**)&w3h, g_w3_h);   cudaGetSymbolAddress((void**)&w3l, g_w3_l);
    cudaGetSymbolAddress((void**)&wf1h, g_wf1_h); cudaGetSymbolAddress((void**)&wf1l, g_wf1_l);
    cudaGetSymbolAddress((void**)&wf2h, g_wf2_h); cudaGetSymbolAddress((void**)&wf2l, g_wf2_l);
    float *bb1, *bb2;
    cudaGetSymbolAddress((void**)&bb1, g_bb1);
    cudaGetSymbolAddress((void**)&bb2, g_bb2);

    const int TB = 256;
    const int nbN = (NN + TB - 1) / TB;
    const int nbE = (NE + TB - 1) / TB;

    // CSR build
    zero_kernel<<<nbN, TB>>>();
    deg_kernel<<<nbE, TB>>>(dst, ea);
    loop_kernel<<<nbN, TB>>>();
    alloc_kernel<<<(NN + 1023) / 1024, 1024>>>();
    csr_kernel<<<nbE, TB>>>(dst);

    // weight pre-splits
    split_kernel<<<(128 * 128 + 255) / 256, 256>>>(fa_w, wfah, wfal, 128 * 128);
    fusepack_kernel<<<(128 * 512 + 255) / 256, 256>>>(r1_w, W1, wb1h, wb1l, 128, 256);
    fusepack_kernel<<<(256 * 512 + 255) / 256, 256>>>(r2_w, W2, wb2h, wb2l, 256, 256);
    split_kernel<<<(256 * 64 + 255) / 256, 256>>>(W3, w3h, w3l, 256 * 64);
    split_kernel<<<(128 * 64 + 255) / 256, 256>>>(ffn_w1, wf1h, wf1l, 128 * 64);
    split_kernel<<<(64 * 64 + 255) / 256, 256>>>(ffn_w2, wf2h, wf2l, 64 * 64);
    biaspack_kernel<<<2, 256>>>(r1_b, r2_b);

    split_kernel<<<(NN * 128 + 255) / 256, 256>>>(x, xh, xl, NN * 128);

    {   // gate: splits of gx only (N=128 -> gemm4)
        dim3 g(128 / 128, (NN + 127) / 128);
        gemm4<EP_GATE, true, false><<<g, 256>>>(xh, xl, wfah, wfal, fa_b, x,
                                                nullptr, gxh, gxl, NN, 128, 128);
    }
    {   // ffn1 (N=64 -> gemm2)
        dim3 g(64 / 64, (NN + 127) / 128);
        gemm2<EP_RELU, true, false><<<g, 256>>>(gxh, gxl, wf1h, wf1l, ffn_b1, nullptr,
                                                nullptr, t64h, t64l, NN, 128, 64);
    }
    {   // ffn2 (N=64)
        dim3 g(64 / 64, (NN + 127) / 128);
        gemm2<EP_NONE, false, true><<<g, 256>>>(t64h, t64l, wf2h, wf2l, ffn_b2, nullptr,
                                                zself, nullptr, nullptr, NN, 64, 64);
    }

    // --- layer 1 (N=512 -> gemm4) ---
    {
        dim3 g(512 / 128, (NN + 127) / 128);
        gemm4<EP_NONE, false, true><<<g, 256>>>(gxh, gxl, wb1h, wb1l, bb1, nullptr,
                                                hr, nullptr, nullptr, NN, 128, 512);
    }
    attn_kernel<4><<<(NN * 4 * 32 + TB - 1) / TB, TB>>>(hr + 256, 512, as1, ad1);
    ch_kernel<<<1, 4>>>(We1, ae1, 4, 64);
    agg2<4, 64, true, false><<<NN, 256>>>(hr + 256, 512, src, ea, b1, hr, 512,
                                          nullptr, z1h, z1l);

    // --- layer 2 (N=512 -> gemm4) ---
    {
        dim3 g(512 / 128, (NN + 127) / 128);
        gemm4<EP_NONE, false, true><<<g, 256>>>(z1h, z1l, wb2h, wb2l, bb2, nullptr,
                                                hr, nullptr, nullptr, NN, 256, 512);
    }
    attn_kernel<4><<<(NN * 4 * 32 + TB - 1) / TB, TB>>>(hr + 256, 512, as2, ad2);
    ch_kernel<<<1, 4>>>(We2, ae2, 4, 64);
    agg2<4, 64, true, false><<<NN, 256>>>(hr + 256, 512, src, ea, b2, hr, 512,
                                          nullptr, z2h, z2l);

    // --- layer 3 (N=64 -> gemm2) ---
    {
        dim3 g(64 / 64, (NN + 127) / 128);
        gemm2<EP_NONE, false, true><<<g, 256>>>(z2h, z2l, w3h, w3l, nullptr, nullptr,
                                                h3, nullptr, nullptr, NN, 256, 64);
    }
    attn_kernel<1><<<(NN * 32 + TB - 1) / TB, TB>>>(h3, 64, as3, ad3);
    ch_kernel<<<1, 1>>>(We3, ae3, 1, 64);
    agg2<1, 64, false, true><<<NN, 64>>>(h3, 64, src, ea, b3, zself, 64,
                                         out, nullptr, nullptr);
}

// round 6
// speedup vs baseline: 1.2047x; 1.1196x over previous
#include <cuda_runtime.h>
#include <cuda_bf16.h>
#include <math.h>
#include <stdint.h>

#define NN 50000
#define NE 800000

// ---------------- scratch (device globals) ----------------
__device__ float g_xh[NN * 128], g_xl[NN * 128];
__device__ float g_gxh[NN * 128], g_gxl[NN * 128];
__device__ float g_hr[NN * 512];                           // [res | h] fused layer out
__device__ float g_z1h[NN * 256], g_z1l[NN * 256];
__device__ float g_z2h[NN * 256], g_z2l[NN * 256];
__device__ float g_t64h[NN * 64], g_t64l[NN * 64];
__device__ float g_zself[NN * 64];
__device__ float g_h3[NN * 64];
__device__ float g_asrc[NN * 4];
__device__ float g_adst[NN * 4];
__device__ float g_loop[NN];
__device__ float g_easum[NN];
__device__ int   g_deg[NN];
__device__ int   g_rowstart[NN];
__device__ int   g_cursor[NN];
__device__ int   g_csr[NE];
__device__ float g_ch[4];
__device__ int   g_total;
__device__ float g_wfa_h[128 * 128], g_wfa_l[128 * 128];
__device__ float g_wb1_h[128 * 512], g_wb1_l[128 * 512];
__device__ float g_wb2_h[256 * 512], g_wb2_l[256 * 512];
__device__ float g_w3_h[256 * 64],  g_w3_l[256 * 64];
__device__ float g_wf1_h[128 * 64], g_wf1_l[128 * 64];
__device__ float g_wf2_h[64 * 64],  g_wf2_l[64 * 64];
__device__ float g_bb1[512], g_bb2[512];

__device__ __forceinline__ float sigf(float x) { return 1.f / (1.f + __expf(-x)); }

__device__ __forceinline__ void tf32_split(float x, float& hi, float& lo) {
    uint32_t uh;
    asm("cvt.rna.tf32.f32 %0, %1;" : "=r"(uh) : "f"(x));
    hi = __uint_as_float(uh);
    float r = x - hi;
    uint32_t ul;
    asm("cvt.rna.tf32.f32 %0, %1;" : "=r"(ul) : "f"(r));
    lo = __uint_as_float(ul);
}

__device__ __forceinline__ void mma_tf32(float* c, const uint32_t* a, const uint32_t* b) {
    asm volatile(
        "mma.sync.aligned.m16n8k8.row.col.f32.tf32.tf32.f32 "
        "{%0,%1,%2,%3}, {%4,%5,%6,%7}, {%8,%9}, {%0,%1,%2,%3};\n"
        : "+f"(c[0]), "+f"(c[1]), "+f"(c[2]), "+f"(c[3])
        : "r"(a[0]), "r"(a[1]), "r"(a[2]), "r"(a[3]), "r"(b[0]), "r"(b[1]));
}

// ---------------- pack / split kernels ----------------
__global__ void split_kernel(const float* __restrict__ s, float* __restrict__ dh,
                             float* __restrict__ dl, int n) {
    int i = blockIdx.x * blockDim.x + threadIdx.x;
    if (i < n) { float h, l; tf32_split(s[i], h, l); dh[i] = h; dl[i] = l; }
}
__global__ void fusepack_kernel(const float* __restrict__ A, const float* __restrict__ B,
                                float* __restrict__ dh, float* __restrict__ dl,
                                int rows, int half) {
    int i = blockIdx.x * blockDim.x + threadIdx.x;
    int tot = rows * 2 * half;
    if (i < tot) {
        int r = i / (2 * half), c = i % (2 * half);
        float v = (c < half) ? A[r * half + c] : B[r * half + c - half];
        float h, l; tf32_split(v, h, l); dh[i] = h; dl[i] = l;
    }
}
__global__ void biaspack_kernel(const float* __restrict__ r1b, const float* __restrict__ r2b) {
    int i = blockIdx.x * blockDim.x + threadIdx.x;
    if (i < 512) {
        g_bb1[i] = (i < 256) ? r1b[i] : 0.f;
        g_bb2[i] = (i < 256) ? r2b[i] : 0.f;
    }
}

#define EP_NONE 0
#define EP_GATE 1
#define EP_RELU 2

// ---------------- gemm2db: R3 layout + double-buffered smem ----------------
// BM=128, BN=64, BK=16, 256 threads (8 warps 4x2), warp tile 32x32.
// dynamic smem: [2][128][20] hi + lo for A, [2][64][20] hi + lo for B.
#define A_BUF 2560   // 128*20 floats
#define B_BUF 1280   // 64*20 floats
#define SMEM_DB ((4 * A_BUF + 4 * B_BUF) * 4)   // 61440 bytes

template <int EP, bool SPLITOUT, bool WRITEC>
__global__ __launch_bounds__(256) void gemm2db(
    const float* __restrict__ Agh, const float* __restrict__ Agl,
    const float* __restrict__ Bgh, const float* __restrict__ Bgl,
    const float* __restrict__ bias, const float* __restrict__ gateA,
    float* __restrict__ C, float* __restrict__ Ch, float* __restrict__ Cl,
    int M, int K, int N) {
    extern __shared__ float sm[];
    float* AshB = sm;                      // [2][128][20]
    float* AslB = sm + 2 * A_BUF;
    float* BshB = sm + 4 * A_BUF;          // [2][64][20]
    float* BslB = sm + 4 * A_BUF + 2 * B_BUF;

    const int bm = blockIdx.y * 128, bn = blockIdx.x * 64;
    const int tid = threadIdx.x, lane = tid & 31, wid = tid >> 5;
    const int wm = wid >> 1, wn = wid & 1;
    const int lg = lane >> 2, lt = lane & 3;
    const int ar0 = tid >> 2, as0 = (tid & 3) * 4;
    const int bkk = tid >> 4, bn4 = (tid & 15) * 4;

    float acc[2][4][4];
#pragma unroll
    for (int mt = 0; mt < 2; mt++)
#pragma unroll
        for (int nt = 0; nt < 4; nt++)
#pragma unroll
            for (int j = 0; j < 4; j++) acc[mt][nt][j] = 0.f;

    float4 rah[2], ral[2], rbh, rbl;
    const float4 z4 = make_float4(0.f, 0.f, 0.f, 0.f);

    // prologue: load tile 0 into regs, stage into buffer 0
#pragma unroll
    for (int t = 0; t < 2; t++) {
        int r = ar0 + t * 64;
        if (bm + r < M) {
            rah[t] = *(const float4*)&Agh[(size_t)(bm + r) * K + as0];
            ral[t] = *(const float4*)&Agl[(size_t)(bm + r) * K + as0];
        } else { rah[t] = z4; ral[t] = z4; }
    }
    rbh = *(const float4*)&Bgh[(size_t)bkk * N + bn + bn4];
    rbl = *(const float4*)&Bgl[(size_t)bkk * N + bn + bn4];

    int p = 0;
    {
        float* Ash = AshB; float* Asl = AslB;
        float* Bsh = BshB; float* Bsl = BslB;
#pragma unroll
        for (int t = 0; t < 2; t++) {
            int r = ar0 + t * 64;
            Ash[r * 20 + as0 + 0] = rah[t].x; Ash[r * 20 + as0 + 1] = rah[t].y;
            Ash[r * 20 + as0 + 2] = rah[t].z; Ash[r * 20 + as0 + 3] = rah[t].w;
            Asl[r * 20 + as0 + 0] = ral[t].x; Asl[r * 20 + as0 + 1] = ral[t].y;
            Asl[r * 20 + as0 + 2] = ral[t].z; Asl[r * 20 + as0 + 3] = ral[t].w;
        }
        Bsh[(bn4 + 0) * 20 + bkk] = rbh.x; Bsh[(bn4 + 1) * 20 + bkk] = rbh.y;
        Bsh[(bn4 + 2) * 20 + bkk] = rbh.z; Bsh[(bn4 + 3) * 20 + bkk] = rbh.w;
        Bsl[(bn4 + 0) * 20 + bkk] = rbl.x; Bsl[(bn4 + 1) * 20 + bkk] = rbl.y;
        Bsl[(bn4 + 2) * 20 + bkk] = rbl.z; Bsl[(bn4 + 3) * 20 + bkk] = rbl.w;
    }
    __syncthreads();

    for (int k0 = 0; k0 < K; k0 += 16) {
        const bool more = (k0 + 16 < K);
        if (more) {
            int kn = k0 + 16;
#pragma unroll
            for (int t = 0; t < 2; t++) {
                int r = ar0 + t * 64;
                if (bm + r < M) {
                    rah[t] = *(const float4*)&Agh[(size_t)(bm + r) * K + kn + as0];
                    ral[t] = *(const float4*)&Agl[(size_t)(bm + r) * K + kn + as0];
                } else { rah[t] = z4; ral[t] = z4; }
            }
            rbh = *(const float4*)&Bgh[(size_t)(kn + bkk) * N + bn + bn4];
            rbl = *(const float4*)&Bgl[(size_t)(kn + bkk) * N + bn + bn4];
        }
        // compute on buffer p
        {
            const float* Ash = AshB + p * A_BUF;
            const float* Asl = AslB + p * A_BUF;
            const float* Bsh = BshB + p * B_BUF;
            const float* Bsl = BslB + p * B_BUF;
#pragma unroll
            for (int ks = 0; ks < 16; ks += 8) {
                const int kc = ks + lt;
                uint32_t ah[2][4], al[2][4], bh[4][2], bl[4][2];
#pragma unroll
                for (int mt = 0; mt < 2; mt++) {
                    int r = wm * 32 + mt * 16 + lg;
                    ah[mt][0] = __float_as_uint(Ash[r * 20 + kc]);
                    ah[mt][1] = __float_as_uint(Ash[(r + 8) * 20 + kc]);
                    ah[mt][2] = __float_as_uint(Ash[r * 20 + kc + 4]);
                    ah[mt][3] = __float_as_uint(Ash[(r + 8) * 20 + kc + 4]);
                    al[mt][0] = __float_as_uint(Asl[r * 20 + kc]);
                    al[mt][1] = __float_as_uint(Asl[(r + 8) * 20 + kc]);
                    al[mt][2] = __float_as_uint(Asl[r * 20 + kc + 4]);
                    al[mt][3] = __float_as_uint(Asl[(r + 8) * 20 + kc + 4]);
                }
#pragma unroll
                for (int nt = 0; nt < 4; nt++) {
                    int c = wn * 32 + nt * 8 + lg;
                    bh[nt][0] = __float_as_uint(Bsh[c * 20 + kc]);
                    bh[nt][1] = __float_as_uint(Bsh[c * 20 + kc + 4]);
                    bl[nt][0] = __float_as_uint(Bsl[c * 20 + kc]);
                    bl[nt][1] = __float_as_uint(Bsl[c * 20 + kc + 4]);
                }
#pragma unroll
                for (int mt = 0; mt < 2; mt++)
#pragma unroll
                    for (int nt = 0; nt < 4; nt++) {
                        mma_tf32(acc[mt][nt], ah[mt], bh[nt]);
                        mma_tf32(acc[mt][nt], al[mt], bh[nt]);
                        mma_tf32(acc[mt][nt], ah[mt], bl[nt]);
                    }
            }
        }
        if (more) {
            // stage next tile into the other buffer
            float* Ash = AshB + (p ^ 1) * A_BUF;
            float* Asl = AslB + (p ^ 1) * A_BUF;
            float* Bsh = BshB + (p ^ 1) * B_BUF;
            float* Bsl = BslB + (p ^ 1) * B_BUF;
#pragma unroll
            for (int t = 0; t < 2; t++) {
                int r = ar0 + t * 64;
                Ash[r * 20 + as0 + 0] = rah[t].x; Ash[r * 20 + as0 + 1] = rah[t].y;
                Ash[r * 20 + as0 + 2] = rah[t].z; Ash[r * 20 + as0 + 3] = rah[t].w;
                Asl[r * 20 + as0 + 0] = ral[t].x; Asl[r * 20 + as0 + 1] = ral[t].y;
                Asl[r * 20 + as0 + 2] = ral[t].z; Asl[r * 20 + as0 + 3] = ral[t].w;
            }
            Bsh[(bn4 + 0) * 20 + bkk] = rbh.x; Bsh[(bn4 + 1) * 20 + bkk] = rbh.y;
            Bsh[(bn4 + 2) * 20 + bkk] = rbh.z; Bsh[(bn4 + 3) * 20 + bkk] = rbh.w;
            Bsl[(bn4 + 0) * 20 + bkk] = rbl.x; Bsl[(bn4 + 1) * 20 + bkk] = rbl.y;
            Bsl[(bn4 + 2) * 20 + bkk] = rbl.z; Bsl[(bn4 + 3) * 20 + bkk] = rbl.w;
            __syncthreads();
            p ^= 1;
        }
    }
    // epilogue
#pragma unroll
    for (int mt = 0; mt < 2; mt++) {
        int r0 = bm + wm * 32 + mt * 16 + lg;
#pragma unroll
        for (int nt = 0; nt < 4; nt++) {
            int c0 = bn + wn * 32 + nt * 8 + lt * 2;
#pragma unroll
            for (int j = 0; j < 4; j++) {
                int row = r0 + (j >> 1) * 8;
                int col = c0 + (j & 1);
                if (row >= M) continue;
                float v = acc[mt][nt][j] + (bias ? bias[col] : 0.f);
                if (EP == EP_GATE) v = gateA[(size_t)row * K + col] * sigf(v);
                else if (EP == EP_RELU) v = fmaxf(v, 0.f);
                size_t idx = (size_t)row * N + col;
                if (WRITEC) C[idx] = v;
                if (SPLITOUT) {
                    float h, l; tf32_split(v, h, l);
                    Ch[idx] = h; Cl[idx] = l;
                }
            }
        }
    }
}

// ---------------- CSR build ----------------
__global__ void zero_kernel() {
    int i = blockIdx.x * blockDim.x + threadIdx.x;
    if (i < NN) { g_deg[i] = 0; g_cursor[i] = 0; g_easum[i] = 0.f; }
    if (i == 0) g_total = 0;
}
__global__ void deg_kernel(const int* __restrict__ dst, const float* __restrict__ ea) {
    int e = blockIdx.x * blockDim.x + threadIdx.x;
    if (e < NE) {
        int d = dst[e];
        atomicAdd(&g_deg[d], 1);
        atomicAdd(&g_easum[d], ea[e]);
    }
}
__global__ void loop_kernel() {
    int n = blockIdx.x * blockDim.x + threadIdx.x;
    if (n < NN) g_loop[n] = g_easum[n] / fmaxf((float)g_deg[n], 1.f);
}
__global__ void alloc_kernel() {
    __shared__ int s[1024];
    __shared__ int base;
    int tid = threadIdx.x;
    int i = blockIdx.x * 1024 + tid;
    int v = (i < NN) ? g_deg[i] : 0;
    s[tid] = v;
    __syncthreads();
    for (int off = 1; off < 1024; off <<= 1) {
        int t = (tid >= off) ? s[tid - off] : 0;
        __syncthreads();
        s[tid] += t;
        __syncthreads();
    }
    int incl = s[tid];
    if (tid == 1023) base = atomicAdd(&g_total, s[1023]);
    __syncthreads();
    if (i < NN) g_rowstart[i] = base + incl - v;
}
__global__ void csr_kernel(const int* __restrict__ dst) {
    int e = blockIdx.x * blockDim.x + threadIdx.x;
    if (e < NE) {
        int d = dst[e];
        int pos = atomicAdd(&g_cursor[d], 1);
        g_csr[g_rowstart[d] + pos] = e;
    }
}

// ---------------- attention coefficients ----------------
template <int H>
__global__ void attn_kernel(const float* __restrict__ hbuf, int stride,
                            const float* __restrict__ a_s, const float* __restrict__ a_d) {
    int w = (blockIdx.x * blockDim.x + threadIdx.x) >> 5;
    int lane = threadIdx.x & 31;
    if (w >= NN * H) return;
    int n = w / H, hh = w % H;
    const float* hr = hbuf + (size_t)n * stride + hh * 64;
    float as0 = a_s[hh * 64 + lane], as1 = a_s[hh * 64 + lane + 32];
    float ad0 = a_d[hh * 64 + lane], ad1 = a_d[hh * 64 + lane + 32];
    float h0 = hr[lane], h1 = hr[lane + 32];
    float vs = h0 * as0 + h1 * as1;
    float vd = h0 * ad0 + h1 * ad1;
#pragma unroll
    for (int off = 16; off > 0; off >>= 1) {
        vs += __shfl_down_sync(0xffffffffu, vs, off);
        vd += __shfl_down_sync(0xffffffffu, vd, off);
    }
    if (lane == 0) { g_asrc[w] = vs; g_adst[w] = vd; }
}

__global__ void ch_kernel(const float* __restrict__ We, const float* __restrict__ ae, int H, int C) {
    int h = threadIdx.x;
    if (h < H) {
        float s = 0.f;
        for (int c = 0; c < C; c++) s += We[h * C + c] * ae[h * C + c];
        g_ch[h] = s;
    }
}

// ---------------- per-node softmax aggregation ----------------
template <int H, int C, bool SPLIT, bool WRITEO>
__global__ void agg2(const float* __restrict__ hbuf, int hstride,
                     const int* __restrict__ src, const float* __restrict__ ea,
                     const float* __restrict__ bias,
                     const float* __restrict__ resid, int rstride,
                     float* __restrict__ out, float* __restrict__ outh,
                     float* __restrict__ outl) {
    constexpr int OUT = H * C;
    constexpr int CH = 64;
    __shared__ float s_m[H], s_z[H], s_adst[H], s_chh[H];
    __shared__ float s_alpha[CH * H];
    __shared__ int s_sid[CH];

    const int n = blockIdx.x;
    const int tid = threadIdx.x;
    const int deg = g_deg[n];
    const int rs = g_rowstart[n];
    const int T = deg + 1;
    const float loopv = g_loop[n];

    if (tid < H) { s_adst[tid] = g_adst[n * H + tid]; s_chh[tid] = g_ch[tid]; }

    if (tid < 32) {
        float m[H], zz[H], adst[H], chh[H];
#pragma unroll
        for (int h = 0; h < H; h++) {
            adst[h] = g_adst[n * H + h]; chh[h] = g_ch[h];
            m[h] = -1e30f; zz[h] = 0.f;
        }
        for (int i = tid; i < T; i += 32) {
            int sN; float eav;
            if (i < deg) { int e = g_csr[rs + i]; sN = src[e]; eav = ea[e]; }
            else { sN = n; eav = loopv; }
#pragma unroll
            for (int h = 0; h < H; h++) {
                float v = g_asrc[sN * H + h] + adst[h] + chh[h] * eav;
                v = (v >= 0.f) ? v : 0.2f * v;
                float nm = fmaxf(m[h], v);
                zz[h] = zz[h] * __expf(m[h] - nm) + __expf(v - nm);
                m[h] = nm;
            }
        }
#pragma unroll
        for (int off = 16; off > 0; off >>= 1) {
#pragma unroll
            for (int h = 0; h < H; h++) {
                float om = __shfl_xor_sync(0xffffffffu, m[h], off);
                float oz = __shfl_xor_sync(0xffffffffu, zz[h], off);
                float nm = fmaxf(m[h], om);
                zz[h] = zz[h] * __expf(m[h] - nm) + oz * __expf(om - nm);
                m[h] = nm;
            }
        }
        if (tid == 0) {
#pragma unroll
            for (int h = 0; h < H; h++) { s_m[h] = m[h]; s_z[h] = zz[h]; }
        }
    }
    __syncthreads();

    // gather pass
    const int hh = tid / C;
    float acc = 0.f;
    for (int base = 0; base < T; base += CH) {
        int i = base + tid;
        if (tid < CH && i < T) {
            int sN; float eav;
            if (i < deg) { int e = g_csr[rs + i]; sN = src[e]; eav = ea[e]; }
            else { sN = n; eav = loopv; }
#pragma unroll
            for (int h = 0; h < H; h++) {
                float v = g_asrc[sN * H + h] + s_adst[h] + s_chh[h] * eav;
                v = (v >= 0.f) ? v : 0.2f * v;
                s_alpha[tid * H + h] = __expf(v - s_m[h]) / s_z[h];
            }
            s_sid[tid] = sN;
        }
        __syncthreads();
        int lim = min(CH, T - base);
        for (int j = 0; j < lim; j++)
            acc += s_alpha[j * H + hh] * hbuf[(size_t)s_sid[j] * hstride + tid];
        __syncthreads();
    }
    float v = acc + bias[tid];
    v = (v >= 0.f) ? v : 0.01f * v;
    v += resid[(size_t)n * rstride + tid];
    size_t idx = (size_t)n * OUT + tid;
    if (WRITEO) out[idx] = v;
    if (SPLIT) {
        float h, l; tf32_split(v, h, l);
        outh[idx] = h; outl[idx] = l;
    }
}

// ---------------- driver ----------------
extern "C" void kernel_launch(void* const* d_in, const int* in_sizes, int n_in,
                              void* d_out, int out_size) {
    const float* x     = (const float*)d_in[0];
    const int*   eidx  = (const int*)d_in[1];
    const float* ea    = (const float*)d_in[2];
    const float* fa_w  = (const float*)d_in[3];
    const float* fa_b  = (const float*)d_in[4];
    const float* W1    = (const float*)d_in[5];
    const float* We1   = (const float*)d_in[6];
    const float* as1   = (const float*)d_in[7];
    const float* ad1   = (const float*)d_in[8];
    const float* ae1   = (const float*)d_in[9];
    const float* b1    = (const float*)d_in[10];
    const float* W2    = (const float*)d_in[11];
    const float* We2   = (const float*)d_in[12];
    const float* as2   = (const float*)d_in[13];
    const float* ad2   = (const float*)d_in[14];
    const float* ae2   = (const float*)d_in[15];
    const float* b2    = (const float*)d_in[16];
    const float* W3    = (const float*)d_in[17];
    const float* We3   = (const float*)d_in[18];
    const float* as3   = (const float*)d_in[19];
    const float* ad3   = (const float*)d_in[20];
    const float* ae3   = (const float*)d_in[21];
    const float* b3    = (const float*)d_in[22];
    const float* r1_w  = (const float*)d_in[23];
    const float* r1_b  = (const float*)d_in[24];
    const float* r2_w  = (const float*)d_in[25];
    const float* r2_b  = (const float*)d_in[26];
    const float* ffn_w1 = (const float*)d_in[27];
    const float* ffn_b1 = (const float*)d_in[28];
    const float* ffn_w2 = (const float*)d_in[29];
    const float* ffn_b2 = (const float*)d_in[30];
    float* out = (float*)d_out;

    const int* src = eidx;
    const int* dst = eidx + NE;

    float *xh, *xl, *gxh, *gxl, *hr, *z1h, *z1l, *z2h, *z2l;
    float *t64h, *t64l, *zself, *h3;
    float *wfah, *wfal, *wb1h, *wb1l, *wb2h, *wb2l, *w3h, *w3l, *wf1h, *wf1l, *wf2h, *wf2l;
    cudaGetSymbolAddress((void**)&xh, g_xh);   cudaGetSymbolAddress((void**)&xl, g_xl);
    cudaGetSymbolAddress((void**)&gxh, g_gxh); cudaGetSymbolAddress((void**)&gxl, g_gxl);
    cudaGetSymbolAddress((void**)&hr, g_hr);
    cudaGetSymbolAddress((void**)&z1h, g_z1h); cudaGetSymbolAddress((void**)&z1l, g_z1l);
    cudaGetSymbolAddress((void**)&z2h, g_z2h); cudaGetSymbolAddress((void**)&z2l, g_z2l);
    cudaGetSymbolAddress((void**)&t64h, g_t64h); cudaGetSymbolAddress((void**)&t64l, g_t64l);
    cudaGetSymbolAddress((void**)&zself, g_zself);
    cudaGetSymbolAddress((void**)&h3, g_h3);
    cudaGetSymbolAddress((void**)&wfah, g_wfa_h); cudaGetSymbolAddress((void**)&wfal, g_wfa_l);
    cudaGetSymbolAddress((void**)&wb1h, g_wb1_h); cudaGetSymbolAddress((void**)&wb1l, g_wb1_l);
    cudaGetSymbolAddress((void**)&wb2h, g_wb2_h); cudaGetSymbolAddress((void**)&wb2l, g_wb2_l);
    cudaGetSymbolAddress((void**)&w3h, g_w3_h);   cudaGetSymbolAddress((void**)&w3l, g_w3_l);
    cudaGetSymbolAddress((void**)&wf1h, g_wf1_h); cudaGetSymbolAddress((void**)&wf1l, g_wf1_l);
    cudaGetSymbolAddress((void**)&wf2h, g_wf2_h); cudaGetSymbolAddress((void**)&wf2l, g_wf2_l);
    float *bb1, *bb2;
    cudaGetSymbolAddress((void**)&bb1, g_bb1);
    cudaGetSymbolAddress((void**)&bb2, g_bb2);

    // raise dynamic smem cap for the GEMM instantiations we use
    cudaFuncSetAttribute(gemm2db<EP_GATE, true, false>,
                         cudaFuncAttributeMaxDynamicSharedMemorySize, SMEM_DB);
    cudaFuncSetAttribute(gemm2db<EP_RELU, true, false>,
                         cudaFuncAttributeMaxDynamicSharedMemorySize, SMEM_DB);
    cudaFuncSetAttribute(gemm2db<EP_NONE, false, true>,
                         cudaFuncAttributeMaxDynamicSharedMemorySize, SMEM_DB);

    const int TB = 256;
    const int nbN = (NN + TB - 1) / TB;
    const int nbE = (NE + TB - 1) / TB;

    // ---- launches 1-5: minimal deps for layer-1 GEMM ----
    split_kernel<<<(NN * 128 + 255) / 256, 256>>>(x, xh, xl, NN * 128);          // 1
    split_kernel<<<(128 * 128 + 255) / 256, 256>>>(fa_w, wfah, wfal, 128 * 128); // 2
    {   // 3: gate gemm (N=128)
        dim3 g(128 / 64, (NN + 127) / 128);
        gemm2db<EP_GATE, true, false><<<g, 256, SMEM_DB>>>(xh, xl, wfah, wfal, fa_b, x,
                                                           nullptr, gxh, gxl, NN, 128, 128);
    }
    fusepack_kernel<<<(128 * 512 + 255) / 256, 256>>>(r1_w, W1, wb1h, wb1l, 128, 256); // 4
    biaspack_kernel<<<2, 256>>>(r1_b, r2_b);                                      // 5
    {   // 6: layer-1 GEMM (N=512)  <-- profiled launch (-s 5 -c 1)
        dim3 g(512 / 64, (NN + 127) / 128);
        gemm2db<EP_NONE, false, true><<<g, 256, SMEM_DB>>>(gxh, gxl, wb1h, wb1l, bb1, nullptr,
                                                           hr, nullptr, nullptr, NN, 128, 512);
    }

    // ---- CSR build ----
    zero_kernel<<<nbN, TB>>>();
    deg_kernel<<<nbE, TB>>>(dst, ea);
    loop_kernel<<<nbN, TB>>>();
    alloc_kernel<<<(NN + 1023) / 1024, 1024>>>();
    csr_kernel<<<nbE, TB>>>(dst);

    // ---- remaining weight splits ----
    fusepack_kernel<<<(256 * 512 + 255) / 256, 256>>>(r2_w, W2, wb2h, wb2l, 256, 256);
    split_kernel<<<(256 * 64 + 255) / 256, 256>>>(W3, w3h, w3l, 256 * 64);
    split_kernel<<<(128 * 64 + 255) / 256, 256>>>(ffn_w1, wf1h, wf1l, 128 * 64);
    split_kernel<<<(64 * 64 + 255) / 256, 256>>>(ffn_w2, wf2h, wf2l, 64 * 64);

    // ---- ffn path ----
    {
        dim3 g(64 / 64, (NN + 127) / 128);
        gemm2db<EP_RELU, true, false><<<g, 256, SMEM_DB>>>(gxh, gxl, wf1h, wf1l, ffn_b1, nullptr,
                                                           nullptr, t64h, t64l, NN, 128, 64);
    }
    {
        dim3 g(64 / 64, (NN + 127) / 128);
        gemm2db<EP_NONE, false, true><<<g, 256, SMEM_DB>>>(t64h, t64l, wf2h, wf2l, ffn_b2, nullptr,
                                                           zself, nullptr, nullptr, NN, 64, 64);
    }

    // ---- layer 1 attention + aggregation ----
    attn_kernel<4><<<(NN * 4 * 32 + TB - 1) / TB, TB>>>(hr + 256, 512, as1, ad1);
    ch_kernel<<<1, 4>>>(We1, ae1, 4, 64);
    agg2<4, 64, true, false><<<NN, 256>>>(hr + 256, 512, src, ea, b1, hr, 512,
                                          nullptr, z1h, z1l);

    // ---- layer 2 ----
    {
        dim3 g(512 / 64, (NN + 127) / 128);
        gemm2db<EP_NONE, false, true><<<g, 256, SMEM_DB>>>(z1h, z1l, wb2h, wb2l, bb2, nullptr,
                                                           hr, nullptr, nullptr, NN, 256, 512);
    }
    attn_kernel<4><<<(NN * 4 * 32 + TB - 1) / TB, TB>>>(hr + 256, 512, as2, ad2);
    ch_kernel<<<1, 4>>>(We2, ae2, 4, 64);
    agg2<4, 64, true, false><<<NN, 256>>>(hr + 256, 512, src, ea, b2, hr, 512,
                                          nullptr, z2h, z2l);

    // ---- layer 3 ----
    {
        dim3 g(64 / 64, (NN + 127) / 128);
        gemm2db<EP_NONE, false, true><<<g, 256, SMEM_DB>>>(z2h, z2l, w3h, w3l, nullptr, nullptr,
                                                           h3, nullptr, nullptr, NN, 256, 64);
    }
    attn_kernel<1><<<(NN * 32 + TB - 1) / TB, TB>>>(h3, 64, as3, ad3);
    ch_kernel<<<1, 1>>>(We3, ae3, 1, 64);
    agg2<1, 64, false, true><<<NN, 64>>>(h3, 64, src, ea, b3, zself, 64,
                                         out, nullptr, nullptr);
}

// round 7
// speedup vs baseline: 1.6378x; 1.3595x over previous
#include <cuda_runtime.h>
#include <cuda_bf16.h>
#include <math.h>
#include <stdint.h>

#define NN 50000
#define NE 800000

typedef __nv_bfloat16 bf16;

// ---------------- scratch (device globals) ----------------
__device__ __align__(16) bf16 g_xh[NN * 128], g_xl[NN * 128];
__device__ __align__(16) bf16 g_gxh[NN * 128], g_gxl[NN * 128];
__device__ float g_hr[NN * 512];                          // [res | h] fused layer out
__device__ __align__(16) bf16 g_z1h[NN * 256], g_z1l[NN * 256];
__device__ __align__(16) bf16 g_z2h[NN * 256], g_z2l[NN * 256];
__device__ __align__(16) bf16 g_t64h[NN * 64], g_t64l[NN * 64];
__device__ float g_zself[NN * 64];
__device__ float g_h3[NN * 64];
__device__ float g_asrc[NN * 4];
__device__ float g_adst[NN * 4];
__device__ float g_loop[NN];
__device__ float g_easum[NN];
__device__ int   g_deg[NN];
__device__ int   g_rowstart[NN];
__device__ int   g_cursor[NN];
__device__ int   g_csr[NE];
__device__ float g_ch[4];
__device__ int   g_total;
// transposed [n][k] k-major bf16 weight splits
__device__ __align__(16) bf16 g_wfa_h[128 * 128], g_wfa_l[128 * 128];
__device__ __align__(16) bf16 g_wb1_h[512 * 128], g_wb1_l[512 * 128];
__device__ __align__(16) bf16 g_wb2_h[512 * 256], g_wb2_l[512 * 256];
__device__ __align__(16) bf16 g_w3_h[64 * 256],  g_w3_l[64 * 256];
__device__ __align__(16) bf16 g_wf1_h[64 * 128], g_wf1_l[64 * 128];
__device__ __align__(16) bf16 g_wf2_h[64 * 64],  g_wf2_l[64 * 64];
__device__ float g_bb1[512], g_bb2[512];

__device__ __forceinline__ float sigf(float x) { return 1.f / (1.f + __expf(-x)); }

__device__ __forceinline__ void bf_split(float x, bf16& h, bf16& l) {
    h = __float2bfloat16(x);
    l = __float2bfloat16(x - __bfloat162float(h));
}

__device__ __forceinline__ void mma_bf16(float* c, const uint32_t* a, const uint32_t* b) {
    asm volatile(
        "mma.sync.aligned.m16n8k16.row.col.f32.bf16.bf16.f32 "
        "{%0,%1,%2,%3}, {%4,%5,%6,%7}, {%8,%9}, {%0,%1,%2,%3};\n"
        : "+f"(c[0]), "+f"(c[1]), "+f"(c[2]), "+f"(c[3])
        : "r"(a[0]), "r"(a[1]), "r"(a[2]), "r"(a[3]), "r"(b[0]), "r"(b[1]));
}

// ---------------- pack / split kernels ----------------
__global__ void split_bf_kernel(const float* __restrict__ s, bf16* __restrict__ dh,
                                bf16* __restrict__ dl, int n) {
    int i = blockIdx.x * blockDim.x + threadIdx.x;
    if (i < n) { bf16 h, l; bf_split(s[i], h, l); dh[i] = h; dl[i] = l; }
}
// packall: fa_t (16384) + wb1_t fused (65536) + bb1 (512) + bb2 (512)
__global__ void packall_kernel(const float* __restrict__ fa_w,
                               const float* __restrict__ r1_w, const float* __restrict__ W1,
                               const float* __restrict__ r1_b, const float* __restrict__ r2_b) {
    int i = blockIdx.x * blockDim.x + threadIdx.x;
    if (i < 16384) {
        int n = i >> 7, k = i & 127;
        bf16 h, l; bf_split(fa_w[k * 128 + n], h, l);
        g_wfa_h[i] = h; g_wfa_l[i] = l;
    } else if (i < 16384 + 65536) {
        int j = i - 16384;
        int n = j >> 7, k = j & 127;
        float v = (n < 256) ? r1_w[k * 256 + n] : W1[k * 256 + n - 256];
        bf16 h, l; bf_split(v, h, l);
        g_wb1_h[j] = h; g_wb1_l[j] = l;
    } else if (i < 16384 + 65536 + 512) {
        int j = i - 81920;
        g_bb1[j] = (j < 256) ? r1_b[j] : 0.f;
    } else if (i < 16384 + 65536 + 1024) {
        int j = i - 82432;
        g_bb2[j] = (j < 256) ? r2_b[j] : 0.f;
    }
}
__global__ void packT_kernel(const float* __restrict__ W, bf16* __restrict__ th,
                             bf16* __restrict__ tl, int K_, int N_) {
    int i = blockIdx.x * blockDim.x + threadIdx.x;
    if (i < K_ * N_) {
        int n = i / K_, k = i % K_;
        bf16 h, l; bf_split(W[k * N_ + n], h, l);
        th[i] = h; tl[i] = l;
    }
}
__global__ void packfuseT_kernel(const float* __restrict__ A_, const float* __restrict__ B_,
                                 bf16* __restrict__ th, bf16* __restrict__ tl,
                                 int K_, int half) {
    int i = blockIdx.x * blockDim.x + threadIdx.x;
    if (i < 2 * half * K_) {
        int n = i / K_, k = i % K_;
        float v = (n < half) ? A_[k * half + n] : B_[k * half + n - half];
        bf16 h, l; bf_split(v, h, l);
        th[i] = h; tl[i] = l;
    }
}

#define EP_NONE 0
#define EP_GATE 1
#define EP_RELU 2

// ---------------- gemm5: bf16x3 m16n8k16, BM=128 BN=64 BK=32, double-buffered
// smem (uint32): A [2buf][2split][128][20] = 10240 ; B [2][2][64][20] = 5120
#define SMEM_DB (15360 * 4)

template <int EP, bool SPLITOUT, bool WRITEC>
__global__ __launch_bounds__(256) void gemm5(
    const bf16* __restrict__ Agh, const bf16* __restrict__ Agl,
    const bf16* __restrict__ Bgh, const bf16* __restrict__ Bgl,
    const float* __restrict__ bias, const float* __restrict__ gateA,
    float* __restrict__ C, bf16* __restrict__ Ch, bf16* __restrict__ Cl,
    int M, int K, int N) {
    extern __shared__ uint32_t smu[];
    const int bm = blockIdx.y * 128, bn = blockIdx.x * 64;
    const int tid = threadIdx.x, lane = tid & 31, wid = tid >> 5;
    const int wm = wid >> 1, wn = wid & 1;
    const int lg = lane >> 2, lt = lane & 3;
    const int arow = tid >> 2, q = tid & 3;   // A: rows arow, arow+64, chunk q (16B)
                                              // B: row arow (0..63), chunk q

    float acc[2][4][4];
#pragma unroll
    for (int mt = 0; mt < 2; mt++)
#pragma unroll
        for (int nt = 0; nt < 4; nt++)
#pragma unroll
            for (int j = 0; j < 4; j++) acc[mt][nt][j] = 0.f;

    uint4 rA[2][2], rB[2];
    const uint4 z16 = make_uint4(0u, 0u, 0u, 0u);

    // prologue load k0=0
#pragma unroll
    for (int t = 0; t < 2; t++) {
        int grow = bm + arow + t * 64;
        if (grow < M) {
            rA[t][0] = ((const uint4*)(Agh + (size_t)grow * K))[q];
            rA[t][1] = ((const uint4*)(Agl + (size_t)grow * K))[q];
        } else { rA[t][0] = z16; rA[t][1] = z16; }
    }
    rB[0] = ((const uint4*)(Bgh + (size_t)(bn + arow) * K))[q];
    rB[1] = ((const uint4*)(Bgl + (size_t)(bn + arow) * K))[q];

    int p = 0;
    {
#pragma unroll
        for (int t = 0; t < 2; t++) {
            int row = arow + t * 64;
#pragma unroll
            for (int s = 0; s < 2; s++) {
                uint32_t* d = smu + s * 2560 + row * 20 + q * 4;
                uint4 v = rA[t][s];
                d[0] = v.x; d[1] = v.y; d[2] = v.z; d[3] = v.w;
            }
        }
#pragma unroll
        for (int s = 0; s < 2; s++) {
            uint32_t* d = smu + 10240 + s * 1280 + arow * 20 + q * 4;
            uint4 v = rB[s];
            d[0] = v.x; d[1] = v.y; d[2] = v.z; d[3] = v.w;
        }
    }
    __syncthreads();

    for (int k0 = 0; k0 < K; k0 += 32) {
        const bool more = (k0 + 32 < K);
        if (more) {
            int kn = k0 + 32;
#pragma unroll
            for (int t = 0; t < 2; t++) {
                int grow = bm + arow + t * 64;
                if (grow < M) {
                    rA[t][0] = ((const uint4*)(Agh + (size_t)grow * K + kn))[q];
                    rA[t][1] = ((const uint4*)(Agl + (size_t)grow * K + kn))[q];
                } else { rA[t][0] = z16; rA[t][1] = z16; }
            }
            rB[0] = ((const uint4*)(Bgh + (size_t)(bn + arow) * K + kn))[q];
            rB[1] = ((const uint4*)(Bgl + (size_t)(bn + arow) * K + kn))[q];
        }
        // compute on buffer p
        {
            const uint32_t* Ah = smu + (p * 2 + 0) * 2560;
            const uint32_t* Al = smu + (p * 2 + 1) * 2560;
            const uint32_t* Bh = smu + 10240 + (p * 2 + 0) * 1280;
            const uint32_t* Bl = smu + 10240 + (p * 2 + 1) * 1280;
#pragma unroll
            for (int ks = 0; ks < 2; ks++) {
                const int kp = ks * 8 + lt;
                uint32_t ah[2][4], al[2][4];
#pragma unroll
                for (int mt = 0; mt < 2; mt++) {
                    int r = wm * 32 + mt * 16 + lg;
                    ah[mt][0] = Ah[r * 20 + kp];
                    ah[mt][1] = Ah[(r + 8) * 20 + kp];
                    ah[mt][2] = Ah[r * 20 + kp + 4];
                    ah[mt][3] = Ah[(r + 8) * 20 + kp + 4];
                    al[mt][0] = Al[r * 20 + kp];
                    al[mt][1] = Al[(r + 8) * 20 + kp];
                    al[mt][2] = Al[r * 20 + kp + 4];
                    al[mt][3] = Al[(r + 8) * 20 + kp + 4];
                }
#pragma unroll
                for (int nt = 0; nt < 4; nt++) {
                    int c = wn * 32 + nt * 8 + lg;
                    uint32_t bh[2], bl2[2];
                    bh[0] = Bh[c * 20 + kp];
                    bh[1] = Bh[c * 20 + kp + 4];
                    bl2[0] = Bl[c * 20 + kp];
                    bl2[1] = Bl[c * 20 + kp + 4];
#pragma unroll
                    for (int mt = 0; mt < 2; mt++) {
                        mma_bf16(acc[mt][nt], ah[mt], bh);
                        mma_bf16(acc[mt][nt], al[mt], bh);
                        mma_bf16(acc[mt][nt], ah[mt], bl2);
                    }
                }
            }
        }
        if (more) {
            int pb = p ^ 1;
#pragma unroll
            for (int t = 0; t < 2; t++) {
                int row = arow + t * 64;
#pragma unroll
                for (int s = 0; s < 2; s++) {
                    uint32_t* d = smu + (pb * 2 + s) * 2560 + row * 20 + q * 4;
                    uint4 v = rA[t][s];
                    d[0] = v.x; d[1] = v.y; d[2] = v.z; d[3] = v.w;
                }
            }
#pragma unroll
            for (int s = 0; s < 2; s++) {
                uint32_t* d = smu + 10240 + (pb * 2 + s) * 1280 + arow * 20 + q * 4;
                uint4 v = rB[s];
                d[0] = v.x; d[1] = v.y; d[2] = v.z; d[3] = v.w;
            }
            __syncthreads();
            p = pb;
        }
    }
    // epilogue
#pragma unroll
    for (int mt = 0; mt < 2; mt++) {
        int r0 = bm + wm * 32 + mt * 16 + lg;
#pragma unroll
        for (int nt = 0; nt < 4; nt++) {
            int c0 = bn + wn * 32 + nt * 8 + lt * 2;
#pragma unroll
            for (int j = 0; j < 4; j++) {
                int row = r0 + (j >> 1) * 8;
                int col = c0 + (j & 1);
                if (row >= M) continue;
                float v = acc[mt][nt][j] + (bias ? bias[col] : 0.f);
                if (EP == EP_GATE) v = gateA[(size_t)row * K + col] * sigf(v);
                else if (EP == EP_RELU) v = fmaxf(v, 0.f);
                size_t idx = (size_t)row * N + col;
                if (WRITEC) C[idx] = v;
                if (SPLITOUT) {
                    bf16 h, l; bf_split(v, h, l);
                    Ch[idx] = h; Cl[idx] = l;
                }
            }
        }
    }
}

// ---------------- CSR build ----------------
__global__ void zero_kernel() {
    int i = blockIdx.x * blockDim.x + threadIdx.x;
    if (i < NN) { g_deg[i] = 0; g_cursor[i] = 0; g_easum[i] = 0.f; }
    if (i == 0) g_total = 0;
}
__global__ void deg_kernel(const int* __restrict__ dst, const float* __restrict__ ea) {
    int e = blockIdx.x * blockDim.x + threadIdx.x;
    if (e < NE) {
        int d = dst[e];
        atomicAdd(&g_deg[d], 1);
        atomicAdd(&g_easum[d], ea[e]);
    }
}
__global__ void loop_kernel() {
    int n = blockIdx.x * blockDim.x + threadIdx.x;
    if (n < NN) g_loop[n] = g_easum[n] / fmaxf((float)g_deg[n], 1.f);
}
__global__ void alloc_kernel() {
    __shared__ int s[1024];
    __shared__ int base;
    int tid = threadIdx.x;
    int i = blockIdx.x * 1024 + tid;
    int v = (i < NN) ? g_deg[i] : 0;
    s[tid] = v;
    __syncthreads();
    for (int off = 1; off < 1024; off <<= 1) {
        int t = (tid >= off) ? s[tid - off] : 0;
        __syncthreads();
        s[tid] += t;
        __syncthreads();
    }
    int incl = s[tid];
    if (tid == 1023) base = atomicAdd(&g_total, s[1023]);
    __syncthreads();
    if (i < NN) g_rowstart[i] = base + incl - v;
}
__global__ void csr_kernel(const int* __restrict__ dst) {
    int e = blockIdx.x * blockDim.x + threadIdx.x;
    if (e < NE) {
        int d = dst[e];
        int pos = atomicAdd(&g_cursor[d], 1);
        g_csr[g_rowstart[d] + pos] = e;
    }
}

// ---------------- attention coefficients ----------------
template <int H>
__global__ void attn_kernel(const float* __restrict__ hbuf, int stride,
                            const float* __restrict__ a_s, const float* __restrict__ a_d) {
    int w = (blockIdx.x * blockDim.x + threadIdx.x) >> 5;
    int lane = threadIdx.x & 31;
    if (w >= NN * H) return;
    int n = w / H, hh = w % H;
    const float* hr = hbuf + (size_t)n * stride + hh * 64;
    float as0 = a_s[hh * 64 + lane], as1 = a_s[hh * 64 + lane + 32];
    float ad0 = a_d[hh * 64 + lane], ad1 = a_d[hh * 64 + lane + 32];
    float h0 = hr[lane], h1 = hr[lane + 32];
    float vs = h0 * as0 + h1 * as1;
    float vd = h0 * ad0 + h1 * ad1;
#pragma unroll
    for (int off = 16; off > 0; off >>= 1) {
        vs += __shfl_down_sync(0xffffffffu, vs, off);
        vd += __shfl_down_sync(0xffffffffu, vd, off);
    }
    if (lane == 0) { g_asrc[w] = vs; g_adst[w] = vd; }
}

__global__ void ch_kernel(const float* __restrict__ We, const float* __restrict__ ae, int H, int C) {
    int h = threadIdx.x;
    if (h < H) {
        float s = 0.f;
        for (int c = 0; c < C; c++) s += We[h * C + c] * ae[h * C + c];
        g_ch[h] = s;
    }
}

// ---------------- per-node softmax aggregation ----------------
template <int H, int C, bool SPLIT, bool WRITEO>
__global__ void agg2(const float* __restrict__ hbuf, int hstride,
                     const int* __restrict__ src, const float* __restrict__ ea,
                     const float* __restrict__ bias,
                     const float* __restrict__ resid, int rstride,
                     float* __restrict__ out, bf16* __restrict__ outh,
                     bf16* __restrict__ outl) {
    constexpr int OUT = H * C;
    constexpr int CH = 64;
    __shared__ float s_m[H], s_z[H], s_adst[H], s_chh[H];
    __shared__ float s_alpha[CH * H];
    __shared__ int s_sid[CH];

    const int n = blockIdx.x;
    const int tid = threadIdx.x;
    const int deg = g_deg[n];
    const int rs = g_rowstart[n];
    const int T = deg + 1;
    const float loopv = g_loop[n];

    if (tid < H) { s_adst[tid] = g_adst[n * H + tid]; s_chh[tid] = g_ch[tid]; }

    if (tid < 32) {
        float m[H], zz[H], adst[H], chh[H];
#pragma unroll
        for (int h = 0; h < H; h++) {
            adst[h] = g_adst[n * H + h]; chh[h] = g_ch[h];
            m[h] = -1e30f; zz[h] = 0.f;
        }
        for (int i = tid; i < T; i += 32) {
            int sN; float eav;
            if (i < deg) { int e = g_csr[rs + i]; sN = src[e]; eav = ea[e]; }
            else { sN = n; eav = loopv; }
#pragma unroll
            for (int h = 0; h < H; h++) {
                float v = g_asrc[sN * H + h] + adst[h] + chh[h] * eav;
                v = (v >= 0.f) ? v : 0.2f * v;
                float nm = fmaxf(m[h], v);
                zz[h] = zz[h] * __expf(m[h] - nm) + __expf(v - nm);
                m[h] = nm;
            }
        }
#pragma unroll
        for (int off = 16; off > 0; off >>= 1) {
#pragma unroll
            for (int h = 0; h < H; h++) {
                float om = __shfl_xor_sync(0xffffffffu, m[h], off);
                float oz = __shfl_xor_sync(0xffffffffu, zz[h], off);
                float nm = fmaxf(m[h], om);
                zz[h] = zz[h] * __expf(m[h] - nm) + oz * __expf(om - nm);
                m[h] = nm;
            }
        }
        if (tid == 0) {
#pragma unroll
            for (int h = 0; h < H; h++) { s_m[h] = m[h]; s_z[h] = zz[h]; }
        }
    }
    __syncthreads();

    // gather pass
    const int hh = tid / C;
    float acc = 0.f;
    for (int base = 0; base < T; base += CH) {
        int i = base + tid;
        if (tid < CH && i < T) {
            int sN; float eav;
            if (i < deg) { int e = g_csr[rs + i]; sN = src[e]; eav = ea[e]; }
            else { sN = n; eav = loopv; }
#pragma unroll
            for (int h = 0; h < H; h++) {
                float v = g_asrc[sN * H + h] + s_adst[h] + s_chh[h] * eav;
                v = (v >= 0.f) ? v : 0.2f * v;
                s_alpha[tid * H + h] = __expf(v - s_m[h]) / s_z[h];
            }
            s_sid[tid] = sN;
        }
        __syncthreads();
        int lim = min(CH, T - base);
        for (int j = 0; j < lim; j++)
            acc += s_alpha[j * H + hh] * hbuf[(size_t)s_sid[j] * hstride + tid];
        __syncthreads();
    }
    float v = acc + bias[tid];
    v = (v >= 0.f) ? v : 0.01f * v;
    v += resid[(size_t)n * rstride + tid];
    size_t idx = (size_t)n * OUT + tid;
    if (WRITEO) out[idx] = v;
    if (SPLIT) {
        bf16 h, l; bf_split(v, h, l);
        outh[idx] = h; outl[idx] = l;
    }
}

// ---------------- driver ----------------
extern "C" void kernel_launch(void* const* d_in, const int* in_sizes, int n_in,
                              void* d_out, int out_size) {
    const float* x     = (const float*)d_in[0];
    const int*   eidx  = (const int*)d_in[1];
    const float* ea    = (const float*)d_in[2];
    const float* fa_w  = (const float*)d_in[3];
    const float* fa_b  = (const float*)d_in[4];
    const float* W1    = (const float*)d_in[5];
    const float* We1   = (const float*)d_in[6];
    const float* as1   = (const float*)d_in[7];
    const float* ad1   = (const float*)d_in[8];
    const float* ae1   = (const float*)d_in[9];
    const float* b1    = (const float*)d_in[10];
    const float* W2    = (const float*)d_in[11];
    const float* We2   = (const float*)d_in[12];
    const float* as2   = (const float*)d_in[13];
    const float* ad2   = (const float*)d_in[14];
    const float* ae2   = (const float*)d_in[15];
    const float* b2    = (const float*)d_in[16];
    const float* W3    = (const float*)d_in[17];
    const float* We3   = (const float*)d_in[18];
    const float* as3   = (const float*)d_in[19];
    const float* ad3   = (const float*)d_in[20];
    const float* ae3   = (const float*)d_in[21];
    const float* b3    = (const float*)d_in[22];
    const float* r1_w  = (const float*)d_in[23];
    const float* r1_b  = (const float*)d_in[24];
    const float* r2_w  = (const float*)d_in[25];
    const float* r2_b  = (const float*)d_in[26];
    const float* ffn_w1 = (const float*)d_in[27];
    const float* ffn_b1 = (const float*)d_in[28];
    const float* ffn_w2 = (const float*)d_in[29];
    const float* ffn_b2 = (const float*)d_in[30];
    float* out = (float*)d_out;

    const int* src = eidx;
    const int* dst = eidx + NE;

    bf16 *xh, *xl, *gxh, *gxl, *z1h, *z1l, *z2h, *z2l, *t64h, *t64l;
    bf16 *wfah, *wfal, *wb1h, *wb1l, *wb2h, *wb2l, *w3h, *w3l, *wf1h, *wf1l, *wf2h, *wf2l;
    float *hr, *zself, *h3, *bb1, *bb2;
    cudaGetSymbolAddress((void**)&xh, g_xh);   cudaGetSymbolAddress((void**)&xl, g_xl);
    cudaGetSymbolAddress((void**)&gxh, g_gxh); cudaGetSymbolAddress((void**)&gxl, g_gxl);
    cudaGetSymbolAddress((void**)&hr, g_hr);
    cudaGetSymbolAddress((void**)&z1h, g_z1h); cudaGetSymbolAddress((void**)&z1l, g_z1l);
    cudaGetSymbolAddress((void**)&z2h, g_z2h); cudaGetSymbolAddress((void**)&z2l, g_z2l);
    cudaGetSymbolAddress((void**)&t64h, g_t64h); cudaGetSymbolAddress((void**)&t64l, g_t64l);
    cudaGetSymbolAddress((void**)&zself, g_zself);
    cudaGetSymbolAddress((void**)&h3, g_h3);
    cudaGetSymbolAddress((void**)&wfah, g_wfa_h); cudaGetSymbolAddress((void**)&wfal, g_wfa_l);
    cudaGetSymbolAddress((void**)&wb1h, g_wb1_h); cudaGetSymbolAddress((void**)&wb1l, g_wb1_l);
    cudaGetSymbolAddress((void**)&wb2h, g_wb2_h); cudaGetSymbolAddress((void**)&wb2l, g_wb2_l);
    cudaGetSymbolAddress((void**)&w3h, g_w3_h);   cudaGetSymbolAddress((void**)&w3l, g_w3_l);
    cudaGetSymbolAddress((void**)&wf1h, g_wf1_h); cudaGetSymbolAddress((void**)&wf1l, g_wf1_l);
    cudaGetSymbolAddress((void**)&wf2h, g_wf2_h); cudaGetSymbolAddress((void**)&wf2l, g_wf2_l);
    cudaGetSymbolAddress((void**)&bb1, g_bb1);
    cudaGetSymbolAddress((void**)&bb2, g_bb2);

    cudaFuncSetAttribute(gemm5<EP_GATE, true, false>,
                         cudaFuncAttributeMaxDynamicSharedMemorySize, SMEM_DB);
    cudaFuncSetAttribute(gemm5<EP_RELU, true, false>,
                         cudaFuncAttributeMaxDynamicSharedMemorySize, SMEM_DB);
    cudaFuncSetAttribute(gemm5<EP_NONE, false, true>,
                         cudaFuncAttributeMaxDynamicSharedMemorySize, SMEM_DB);

    const int TB = 256;
    const int nbN = (NN + TB - 1) / TB;
    const int nbE = (NE + TB - 1) / TB;
    const int gy = (NN + 127) / 128;

    // launch 1: all weight prep needed by gate + layer1
    packall_kernel<<<(82944 + 255) / 256, 256>>>(fa_w, r1_w, W1, r1_b, r2_b);
    // launch 2: split x
    split_bf_kernel<<<(NN * 128 + 255) / 256, 256>>>(x, xh, xl, NN * 128);
    // launch 3: gate gemm (N=128)
    gemm5<EP_GATE, true, false><<<dim3(2, gy), 256, SMEM_DB>>>(
        xh, xl, wfah, wfal, fa_b, x, nullptr, gxh, gxl, NN, 128, 128);
    // launch 4: layer-1 GEMM (N=512)  <-- profiled launch
    gemm5<EP_NONE, false, true><<<dim3(8, gy), 256, SMEM_DB>>>(
        gxh, gxl, wb1h, wb1l, bb1, nullptr, hr, nullptr, nullptr, NN, 128, 512);

    // CSR build
    zero_kernel<<<nbN, TB>>>();
    deg_kernel<<<nbE, TB>>>(dst, ea);
    loop_kernel<<<nbN, TB>>>();
    alloc_kernel<<<(NN + 1023) / 1024, 1024>>>();
    csr_kernel<<<nbE, TB>>>(dst);

    // remaining weight packs
    packfuseT_kernel<<<(512 * 256 + 255) / 256, 256>>>(r2_w, W2, wb2h, wb2l, 256, 256);
    packT_kernel<<<(64 * 256 + 255) / 256, 256>>>(W3, w3h, w3l, 256, 64);
    packT_kernel<<<(64 * 128 + 255) / 256, 256>>>(ffn_w1, wf1h, wf1l, 128, 64);
    packT_kernel<<<(64 * 64 + 255) / 256, 256>>>(ffn_w2, wf2h, wf2l, 64, 64);

    // ffn path
    gemm5<EP_RELU, true, false><<<dim3(1, gy), 256, SMEM_DB>>>(
        gxh, gxl, wf1h, wf1l, ffn_b1, nullptr, nullptr, t64h, t64l, NN, 128, 64);
    gemm5<EP_NONE, false, true><<<dim3(1, gy), 256, SMEM_DB>>>(
        t64h, t64l, wf2h, wf2l, ffn_b2, nullptr, zself, nullptr, nullptr, NN, 64, 64);

    // layer 1 attention + aggregation
    attn_kernel<4><<<(NN * 4 * 32 + TB - 1) / TB, TB>>>(hr + 256, 512, as1, ad1);
    ch_kernel<<<1, 4>>>(We1, ae1, 4, 64);
    agg2<4, 64, true, false><<<NN, 256>>>(hr + 256, 512, src, ea, b1, hr, 512,
                                          nullptr, z1h, z1l);

    // layer 2
    gemm5<EP_NONE, false, true><<<dim3(8, gy), 256, SMEM_DB>>>(
        z1h, z1l, wb2h, wb2l, bb2, nullptr, hr, nullptr, nullptr, NN, 256, 512);
    attn_kernel<4><<<(NN * 4 * 32 + TB - 1) / TB, TB>>>(hr + 256, 512, as2, ad2);
    ch_kernel<<<1, 4>>>(We2, ae2, 4, 64);
    agg2<4, 64, true, false><<<NN, 256>>>(hr + 256, 512, src, ea, b2, hr, 512,
                                          nullptr, z2h, z2l);

    // layer 3
    gemm5<EP_NONE, false, true><<<dim3(1, gy), 256, SMEM_DB>>>(
        z2h, z2l, w3h, w3l, nullptr, nullptr, h3, nullptr, nullptr, NN, 256, 64);
    attn_kernel<1><<<(NN * 32 + TB - 1) / TB, TB>>>(h3, 64, as3, ad3);
    ch_kernel<<<1, 1>>>(We3, ae3, 1, 64);
    agg2<1, 64, false, true><<<NN, 64>>>(h3, 64, src, ea, b3, zself, 64,
                                         out, nullptr, nullptr);
}

// round 8
// speedup vs baseline: 1.7133x; 1.0461x over previous
#include <cuda_runtime.h>
#include <cuda_bf16.h>
#include <math.h>
#include <stdint.h>

#define NN 50000
#define NE 800000

typedef __nv_bfloat16 bf16;

// ---------------- scratch (device globals) ----------------
__device__ __align__(16) bf16 g_xh[NN * 128], g_xl[NN * 128];
__device__ __align__(16) bf16 g_gxh[NN * 128], g_gxl[NN * 128];
__device__ float g_hr[NN * 512];                          // [res | h] fused layer out
__device__ __align__(16) bf16 g_z1h[NN * 256], g_z1l[NN * 256];
__device__ __align__(16) bf16 g_z2h[NN * 256], g_z2l[NN * 256];
__device__ __align__(16) bf16 g_t64h[NN * 64], g_t64l[NN * 64];
__device__ float g_zself[NN * 64];
__device__ float g_h3[NN * 64];
__device__ float g_asrc[NN * 4];
__device__ float g_adst[NN * 4];
__device__ float g_loop[NN];
__device__ float g_easum[NN];
__device__ int   g_deg[NN];
__device__ int   g_rowstart[NN];
__device__ int   g_cursor[NN];
__device__ int   g_csr[NE];
__device__ float g_ch[4];
__device__ int   g_total;
// transposed [n][k] k-major bf16 weight splits
__device__ __align__(16) bf16 g_wfa_h[128 * 128], g_wfa_l[128 * 128];
__device__ __align__(16) bf16 g_wb1_h[512 * 128], g_wb1_l[512 * 128];
__device__ __align__(16) bf16 g_wb2_h[512 * 256], g_wb2_l[512 * 256];
__device__ __align__(16) bf16 g_w3_h[64 * 256],  g_w3_l[64 * 256];
__device__ __align__(16) bf16 g_wf1_h[64 * 128], g_wf1_l[64 * 128];
__device__ __align__(16) bf16 g_wf2_h[64 * 64],  g_wf2_l[64 * 64];
__device__ float g_bb1[512], g_bb2[512];

__device__ __forceinline__ float sigf(float x) { return 1.f / (1.f + __expf(-x)); }

__device__ __forceinline__ void bf_split(float x, bf16& h, bf16& l) {
    h = __float2bfloat16(x);
    l = __float2bfloat16(x - __bfloat162float(h));
}

__device__ __forceinline__ void mma_bf16(float* c, const uint32_t* a, const uint32_t* b) {
    asm volatile(
        "mma.sync.aligned.m16n8k16.row.col.f32.bf16.bf16.f32 "
        "{%0,%1,%2,%3}, {%4,%5,%6,%7}, {%8,%9}, {%0,%1,%2,%3};\n"
        : "+f"(c[0]), "+f"(c[1]), "+f"(c[2]), "+f"(c[3])
        : "r"(a[0]), "r"(a[1]), "r"(a[2]), "r"(a[3]), "r"(b[0]), "r"(b[1]));
}

__device__ __forceinline__ void cp16(uint32_t dst, const void* src, int sz) {
    asm volatile("cp.async.cg.shared.global [%0], [%1], 16, %2;\n"
                 :: "r"(dst), "l"(src), "r"(sz));
}
__device__ __forceinline__ void cp_commit() {
    asm volatile("cp.async.commit_group;\n");
}
template <int N>
__device__ __forceinline__ void cp_wait() {
    asm volatile("cp.async.wait_group %0;\n" :: "n"(N));
}

// ---------------- pack / split kernels ----------------
__global__ void split_bf_kernel(const float* __restrict__ s, bf16* __restrict__ dh,
                                bf16* __restrict__ dl, int n) {
    int i = blockIdx.x * blockDim.x + threadIdx.x;
    if (i < n) { bf16 h, l; bf_split(s[i], h, l); dh[i] = h; dl[i] = l; }
}
__global__ void packall_kernel(const float* __restrict__ fa_w,
                               const float* __restrict__ r1_w, const float* __restrict__ W1,
                               const float* __restrict__ r1_b, const float* __restrict__ r2_b) {
    int i = blockIdx.x * blockDim.x + threadIdx.x;
    if (i < 16384) {
        int n = i >> 7, k = i & 127;
        bf16 h, l; bf_split(fa_w[k * 128 + n], h, l);
        g_wfa_h[i] = h; g_wfa_l[i] = l;
    } else if (i < 16384 + 65536) {
        int j = i - 16384;
        int n = j >> 7, k = j & 127;
        float v = (n < 256) ? r1_w[k * 256 + n] : W1[k * 256 + n - 256];
        bf16 h, l; bf_split(v, h, l);
        g_wb1_h[j] = h; g_wb1_l[j] = l;
    } else if (i < 16384 + 65536 + 512) {
        int j = i - 81920;
        g_bb1[j] = (j < 256) ? r1_b[j] : 0.f;
    } else if (i < 16384 + 65536 + 1024) {
        int j = i - 82432;
        g_bb2[j] = (j < 256) ? r2_b[j] : 0.f;
    }
}
__global__ void packT_kernel(const float* __restrict__ W, bf16* __restrict__ th,
                             bf16* __restrict__ tl, int K_, int N_) {
    int i = blockIdx.x * blockDim.x + threadIdx.x;
    if (i < K_ * N_) {
        int n = i / K_, k = i % K_;
        bf16 h, l; bf_split(W[k * N_ + n], h, l);
        th[i] = h; tl[i] = l;
    }
}
__global__ void packfuseT_kernel(const float* __restrict__ A_, const float* __restrict__ B_,
                                 bf16* __restrict__ th, bf16* __restrict__ tl,
                                 int K_, int half) {
    int i = blockIdx.x * blockDim.x + threadIdx.x;
    if (i < 2 * half * K_) {
        int n = i / K_, k = i % K_;
        float v = (n < half) ? A_[k * half + n] : B_[k * half + n - half];
        bf16 h, l; bf_split(v, h, l);
        th[i] = h; tl[i] = l;
    }
}

#define EP_NONE 0
#define EP_GATE 1
#define EP_RELU 2

// ---------------- gemm5: bf16x3 m16n8k16, BM=128 BN=64 BK=32 (N=64 cases) --
#define SMEM_DB (15360 * 4)

template <int EP, bool SPLITOUT, bool WRITEC>
__global__ __launch_bounds__(256) void gemm5(
    const bf16* __restrict__ Agh, const bf16* __restrict__ Agl,
    const bf16* __restrict__ Bgh, const bf16* __restrict__ Bgl,
    const float* __restrict__ bias, const float* __restrict__ gateA,
    float* __restrict__ C, bf16* __restrict__ Ch, bf16* __restrict__ Cl,
    int M, int K, int N) {
    extern __shared__ uint32_t smu[];
    const int bm = blockIdx.y * 128, bn = blockIdx.x * 64;
    const int tid = threadIdx.x, lane = tid & 31, wid = tid >> 5;
    const int wm = wid >> 1, wn = wid & 1;
    const int lg = lane >> 2, lt = lane & 3;
    const int arow = tid >> 2, q = tid & 3;

    float acc[2][4][4];
#pragma unroll
    for (int mt = 0; mt < 2; mt++)
#pragma unroll
        for (int nt = 0; nt < 4; nt++)
#pragma unroll
            for (int j = 0; j < 4; j++) acc[mt][nt][j] = 0.f;

    uint4 rA[2][2], rB[2];
    const uint4 z16 = make_uint4(0u, 0u, 0u, 0u);

#pragma unroll
    for (int t = 0; t < 2; t++) {
        int grow = bm + arow + t * 64;
        if (grow < M) {
            rA[t][0] = ((const uint4*)(Agh + (size_t)grow * K))[q];
            rA[t][1] = ((const uint4*)(Agl + (size_t)grow * K))[q];
        } else { rA[t][0] = z16; rA[t][1] = z16; }
    }
    rB[0] = ((const uint4*)(Bgh + (size_t)(bn + arow) * K))[q];
    rB[1] = ((const uint4*)(Bgl + (size_t)(bn + arow) * K))[q];

    int p = 0;
    {
#pragma unroll
        for (int t = 0; t < 2; t++) {
            int row = arow + t * 64;
#pragma unroll
            for (int s = 0; s < 2; s++) {
                uint32_t* d = smu + s * 2560 + row * 20 + q * 4;
                uint4 v = rA[t][s];
                d[0] = v.x; d[1] = v.y; d[2] = v.z; d[3] = v.w;
            }
        }
#pragma unroll
        for (int s = 0; s < 2; s++) {
            uint32_t* d = smu + 10240 + s * 1280 + arow * 20 + q * 4;
            uint4 v = rB[s];
            d[0] = v.x; d[1] = v.y; d[2] = v.z; d[3] = v.w;
        }
    }
    __syncthreads();

    for (int k0 = 0; k0 < K; k0 += 32) {
        const bool more = (k0 + 32 < K);
        if (more) {
            int kn = k0 + 32;
#pragma unroll
            for (int t = 0; t < 2; t++) {
                int grow = bm + arow + t * 64;
                if (grow < M) {
                    rA[t][0] = ((const uint4*)(Agh + (size_t)grow * K + kn))[q];
                    rA[t][1] = ((const uint4*)(Agl + (size_t)grow * K + kn))[q];
                } else { rA[t][0] = z16; rA[t][1] = z16; }
            }
            rB[0] = ((const uint4*)(Bgh + (size_t)(bn + arow) * K + kn))[q];
            rB[1] = ((const uint4*)(Bgl + (size_t)(bn + arow) * K + kn))[q];
        }
        {
            const uint32_t* Ah = smu + (p * 2 + 0) * 2560;
            const uint32_t* Al = smu + (p * 2 + 1) * 2560;
            const uint32_t* Bh = smu + 10240 + (p * 2 + 0) * 1280;
            const uint32_t* Bl = smu + 10240 + (p * 2 + 1) * 1280;
#pragma unroll
            for (int ks = 0; ks < 2; ks++) {
                const int kp = ks * 8 + lt;
                uint32_t ah[2][4], al[2][4];
#pragma unroll
                for (int mt = 0; mt < 2; mt++) {
                    int r = wm * 32 + mt * 16 + lg;
                    ah[mt][0] = Ah[r * 20 + kp];
                    ah[mt][1] = Ah[(r + 8) * 20 + kp];
                    ah[mt][2] = Ah[r * 20 + kp + 4];
                    ah[mt][3] = Ah[(r + 8) * 20 + kp + 4];
                    al[mt][0] = Al[r * 20 + kp];
                    al[mt][1] = Al[(r + 8) * 20 + kp];
                    al[mt][2] = Al[r * 20 + kp + 4];
                    al[mt][3] = Al[(r + 8) * 20 + kp + 4];
                }
#pragma unroll
                for (int nt = 0; nt < 4; nt++) {
                    int c = wn * 32 + nt * 8 + lg;
                    uint32_t bh[2], bl2[2];
                    bh[0] = Bh[c * 20 + kp];
                    bh[1] = Bh[c * 20 + kp + 4];
                    bl2[0] = Bl[c * 20 + kp];
                    bl2[1] = Bl[c * 20 + kp + 4];
#pragma unroll
                    for (int mt = 0; mt < 2; mt++) {
                        mma_bf16(acc[mt][nt], ah[mt], bh);
                        mma_bf16(acc[mt][nt], al[mt], bh);
                        mma_bf16(acc[mt][nt], ah[mt], bl2);
                    }
                }
            }
        }
        if (more) {
            int pb = p ^ 1;
#pragma unroll
            for (int t = 0; t < 2; t++) {
                int row = arow + t * 64;
#pragma unroll
                for (int s = 0; s < 2; s++) {
                    uint32_t* d = smu + (pb * 2 + s) * 2560 + row * 20 + q * 4;
                    uint4 v = rA[t][s];
                    d[0] = v.x; d[1] = v.y; d[2] = v.z; d[3] = v.w;
                }
            }
#pragma unroll
            for (int s = 0; s < 2; s++) {
                uint32_t* d = smu + 10240 + (pb * 2 + s) * 1280 + arow * 20 + q * 4;
                uint4 v = rB[s];
                d[0] = v.x; d[1] = v.y; d[2] = v.z; d[3] = v.w;
            }
            __syncthreads();
            p = pb;
        }
    }
#pragma unroll
    for (int mt = 0; mt < 2; mt++) {
        int r0 = bm + wm * 32 + mt * 16 + lg;
#pragma unroll
        for (int nt = 0; nt < 4; nt++) {
            int c0 = bn + wn * 32 + nt * 8 + lt * 2;
#pragma unroll
            for (int j = 0; j < 4; j++) {
                int row = r0 + (j >> 1) * 8;
                int col = c0 + (j & 1);
                if (row >= M) continue;
                float v = acc[mt][nt][j] + (bias ? bias[col] : 0.f);
                if (EP == EP_GATE) v = gateA[(size_t)row * K + col] * sigf(v);
                else if (EP == EP_RELU) v = fmaxf(v, 0.f);
                size_t idx = (size_t)row * N + col;
                if (WRITEC) C[idx] = v;
                if (SPLITOUT) {
                    bf16 h, l; bf_split(v, h, l);
                    Ch[idx] = h; Cl[idx] = l;
                }
            }
        }
    }
}

// ---------------- gemm6: BM=128 BN=128, 4 warps 64x64, cp.async double-buf --
// smem u32: A [2buf][2split][128][20] = 10240, B same at +10240. 80KB.
#define SMEM2 (20480 * 4)

template <int EP, bool SPLITOUT, bool WRITEC>
__global__ __launch_bounds__(128) void gemm6(
    const bf16* __restrict__ Agh, const bf16* __restrict__ Agl,
    const bf16* __restrict__ Bgh, const bf16* __restrict__ Bgl,
    const float* __restrict__ bias, const float* __restrict__ gateA,
    float* __restrict__ C, bf16* __restrict__ Ch, bf16* __restrict__ Cl,
    int M, int K, int N) {
    extern __shared__ uint32_t smu[];
    const int bm = blockIdx.y * 128, bn = blockIdx.x * 128;
    const int tid = threadIdx.x, lane = tid & 31, wid = tid >> 5;
    const int wm = wid >> 1, wn = wid & 1;
    const int lg = lane >> 2, lt = lane & 3;
    const uint32_t smb = (uint32_t)__cvta_generic_to_shared(smu);

    float acc[4][8][4];
#pragma unroll
    for (int mt = 0; mt < 4; mt++)
#pragma unroll
        for (int nt = 0; nt < 8; nt++)
#pragma unroll
            for (int j = 0; j < 4; j++) acc[mt][nt][j] = 0.f;

    // issue one k32 tile into buffer p via cp.async (16 x 16B per thread)
    auto issue = [&](int p, int k0) {
#pragma unroll
        for (int i = 0; i < 4; i++) {
            int idx = tid + i * 128;
            int row = idx >> 2, q = idx & 3;
            // A
            int grow = bm + row;
            int sz = (grow < M) ? 16 : 0;
            int cg = (grow < M) ? grow : (M - 1);
            cp16(smb + (((p * 2 + 0) * 2560 + row * 20 + q * 4) << 2),
                 Agh + (size_t)cg * K + k0 + q * 8, sz);
            cp16(smb + (((p * 2 + 1) * 2560 + row * 20 + q * 4) << 2),
                 Agl + (size_t)cg * K + k0 + q * 8, sz);
            // B (bn+row always < N)
            cp16(smb + ((10240 + (p * 2 + 0) * 2560 + row * 20 + q * 4) << 2),
                 Bgh + (size_t)(bn + row) * K + k0 + q * 8, 16);
            cp16(smb + ((10240 + (p * 2 + 1) * 2560 + row * 20 + q * 4) << 2),
                 Bgl + (size_t)(bn + row) * K + k0 + q * 8, 16);
        }
        cp_commit();
    };

    issue(0, 0);
    int p = 0;
    for (int k0 = 0; k0 < K; k0 += 32) {
        const bool more = (k0 + 32 < K);
        if (more) issue(p ^ 1, k0 + 32);
        if (more) cp_wait<1>(); else cp_wait<0>();
        __syncthreads();
        {
            const uint32_t* Ah = smu + (p * 2 + 0) * 2560;
            const uint32_t* Al = smu + (p * 2 + 1) * 2560;
            const uint32_t* Bh = smu + 10240 + (p * 2 + 0) * 2560;
            const uint32_t* Bl = smu + 10240 + (p * 2 + 1) * 2560;
#pragma unroll
            for (int ks = 0; ks < 2; ks++) {
                const int kp = ks * 8 + lt;
                uint32_t ah[4][4], al[4][4];
#pragma unroll
                for (int mt = 0; mt < 4; mt++) {
                    int r = wm * 64 + mt * 16 + lg;
                    ah[mt][0] = Ah[r * 20 + kp];
                    ah[mt][1] = Ah[(r + 8) * 20 + kp];
                    ah[mt][2] = Ah[r * 20 + kp + 4];
                    ah[mt][3] = Ah[(r + 8) * 20 + kp + 4];
                    al[mt][0] = Al[r * 20 + kp];
                    al[mt][1] = Al[(r + 8) * 20 + kp];
                    al[mt][2] = Al[r * 20 + kp + 4];
                    al[mt][3] = Al[(r + 8) * 20 + kp + 4];
                }
#pragma unroll
                for (int nt = 0; nt < 8; nt++) {
                    int c = wn * 64 + nt * 8 + lg;
                    uint32_t bh[2], bl2[2];
                    bh[0] = Bh[c * 20 + kp];
                    bh[1] = Bh[c * 20 + kp + 4];
                    bl2[0] = Bl[c * 20 + kp];
                    bl2[1] = Bl[c * 20 + kp + 4];
#pragma unroll
                    for (int mt = 0; mt < 4; mt++) {
                        mma_bf16(acc[mt][nt], ah[mt], bh);
                        mma_bf16(acc[mt][nt], al[mt], bh);
                        mma_bf16(acc[mt][nt], ah[mt], bl2);
                    }
                }
            }
        }
        __syncthreads();   // all warps done reading buf p before it is refilled
        p ^= 1;
    }
    // epilogue
#pragma unroll
    for (int mt = 0; mt < 4; mt++) {
        int r0 = bm + wm * 64 + mt * 16 + lg;
#pragma unroll
        for (int nt = 0; nt < 8; nt++) {
            int c0 = bn + wn * 64 + nt * 8 + lt * 2;
#pragma unroll
            for (int j = 0; j < 4; j++) {
                int row = r0 + (j >> 1) * 8;
                int col = c0 + (j & 1);
                if (row >= M) continue;
                float v = acc[mt][nt][j] + (bias ? bias[col] : 0.f);
                if (EP == EP_GATE) v = gateA[(size_t)row * K + col] * sigf(v);
                else if (EP == EP_RELU) v = fmaxf(v, 0.f);
                size_t idx = (size_t)row * N + col;
                if (WRITEC) C[idx] = v;
                if (SPLITOUT) {
                    bf16 h, l; bf_split(v, h, l);
                    Ch[idx] = h; Cl[idx] = l;
                }
            }
        }
    }
}

// ---------------- CSR build ----------------
__global__ void zero_kernel() {
    int i = blockIdx.x * blockDim.x + threadIdx.x;
    if (i < NN) { g_deg[i] = 0; g_cursor[i] = 0; g_easum[i] = 0.f; }
    if (i == 0) g_total = 0;
}
__global__ void deg_kernel(const int* __restrict__ dst, const float* __restrict__ ea) {
    int e = blockIdx.x * blockDim.x + threadIdx.x;
    if (e < NE) {
        int d = dst[e];
        atomicAdd(&g_deg[d], 1);
        atomicAdd(&g_easum[d], ea[e]);
    }
}
__global__ void loop_kernel() {
    int n = blockIdx.x * blockDim.x + threadIdx.x;
    if (n < NN) g_loop[n] = g_easum[n] / fmaxf((float)g_deg[n], 1.f);
}
__global__ void alloc_kernel() {
    __shared__ int s[1024];
    __shared__ int base;
    int tid = threadIdx.x;
    int i = blockIdx.x * 1024 + tid;
    int v = (i < NN) ? g_deg[i] : 0;
    s[tid] = v;
    __syncthreads();
    for (int off = 1; off < 1024; off <<= 1) {
        int t = (tid >= off) ? s[tid - off] : 0;
        __syncthreads();
        s[tid] += t;
        __syncthreads();
    }
    int incl = s[tid];
    if (tid == 1023) base = atomicAdd(&g_total, s[1023]);
    __syncthreads();
    if (i < NN) g_rowstart[i] = base + incl - v;
}
__global__ void csr_kernel(const int* __restrict__ dst) {
    int e = blockIdx.x * blockDim.x + threadIdx.x;
    if (e < NE) {
        int d = dst[e];
        int pos = atomicAdd(&g_cursor[d], 1);
        g_csr[g_rowstart[d] + pos] = e;
    }
}

// ---------------- attention coefficients ----------------
template <int H>
__global__ void attn_kernel(const float* __restrict__ hbuf, int stride,
                            const float* __restrict__ a_s, const float* __restrict__ a_d) {
    int w = (blockIdx.x * blockDim.x + threadIdx.x) >> 5;
    int lane = threadIdx.x & 31;
    if (w >= NN * H) return;
    int n = w / H, hh = w % H;
    const float* hr = hbuf + (size_t)n * stride + hh * 64;
    float as0 = a_s[hh * 64 + lane], as1 = a_s[hh * 64 + lane + 32];
    float ad0 = a_d[hh * 64 + lane], ad1 = a_d[hh * 64 + lane + 32];
    float h0 = hr[lane], h1 = hr[lane + 32];
    float vs = h0 * as0 + h1 * as1;
    float vd = h0 * ad0 + h1 * ad1;
#pragma unroll
    for (int off = 16; off > 0; off >>= 1) {
        vs += __shfl_down_sync(0xffffffffu, vs, off);
        vd += __shfl_down_sync(0xffffffffu, vd, off);
    }
    if (lane == 0) { g_asrc[w] = vs; g_adst[w] = vd; }
}

__global__ void ch_kernel(const float* __restrict__ We, const float* __restrict__ ae, int H, int C) {
    int h = threadIdx.x;
    if (h < H) {
        float s = 0.f;
        for (int c = 0; c < C; c++) s += We[h * C + c] * ae[h * C + c];
        g_ch[h] = s;
    }
}

// ---------------- per-node softmax aggregation ----------------
template <int H, int C, bool SPLIT, bool WRITEO>
__global__ void agg2(const float* __restrict__ hbuf, int hstride,
                     const int* __restrict__ src, const float* __restrict__ ea,
                     const float* __restrict__ bias,
                     const float* __restrict__ resid, int rstride,
                     float* __restrict__ out, bf16* __restrict__ outh,
                     bf16* __restrict__ outl) {
    constexpr int OUT = H * C;
    constexpr int CH = 64;
    __shared__ float s_m[H], s_z[H], s_adst[H], s_chh[H];
    __shared__ float s_alpha[CH * H];
    __shared__ int s_sid[CH];

    const int n = blockIdx.x;
    const int tid = threadIdx.x;
    const int deg = g_deg[n];
    const int rs = g_rowstart[n];
    const int T = deg + 1;
    const float loopv = g_loop[n];

    if (tid < H) { s_adst[tid] = g_adst[n * H + tid]; s_chh[tid] = g_ch[tid]; }

    if (tid < 32) {
        float m[H], zz[H], adst[H], chh[H];
#pragma unroll
        for (int h = 0; h < H; h++) {
            adst[h] = g_adst[n * H + h]; chh[h] = g_ch[h];
            m[h] = -1e30f; zz[h] = 0.f;
        }
        for (int i = tid; i < T; i += 32) {
            int sN; float eav;
            if (i < deg) { int e = g_csr[rs + i]; sN = src[e]; eav = ea[e]; }
            else { sN = n; eav = loopv; }
#pragma unroll
            for (int h = 0; h < H; h++) {
                float v = g_asrc[sN * H + h] + adst[h] + chh[h] * eav;
                v = (v >= 0.f) ? v : 0.2f * v;
                float nm = fmaxf(m[h], v);
                zz[h] = zz[h] * __expf(m[h] - nm) + __expf(v - nm);
                m[h] = nm;
            }
        }
#pragma unroll
        for (int off = 16; off > 0; off >>= 1) {
#pragma unroll
            for (int h = 0; h < H; h++) {
                float om = __shfl_xor_sync(0xffffffffu, m[h], off);
                float oz = __shfl_xor_sync(0xffffffffu, zz[h], off);
                float nm = fmaxf(m[h], om);
                zz[h] = zz[h] * __expf(m[h] - nm) + oz * __expf(om - nm);
                m[h] = nm;
            }
        }
        if (tid == 0) {
#pragma unroll
            for (int h = 0; h < H; h++) { s_m[h] = m[h]; s_z[h] = zz[h]; }
        }
    }
    __syncthreads();

    // gather pass
    const int hh = tid / C;
    float acc = 0.f;
    for (int base = 0; base < T; base += CH) {
        int i = base + tid;
        if (tid < CH && i < T) {
            int sN; float eav;
            if (i < deg) { int e = g_csr[rs + i]; sN = src[e]; eav = ea[e]; }
            else { sN = n; eav = loopv; }
#pragma unroll
            for (int h = 0; h < H; h++) {
                float v = g_asrc[sN * H + h] + s_adst[h] + s_chh[h] * eav;
                v = (v >= 0.f) ? v : 0.2f * v;
                s_alpha[tid * H + h] = __expf(v - s_m[h]) / s_z[h];
            }
            s_sid[tid] = sN;
        }
        __syncthreads();
        int lim = min(CH, T - base);
        for (int j = 0; j < lim; j++)
            acc += s_alpha[j * H + hh] * hbuf[(size_t)s_sid[j] * hstride + tid];
        __syncthreads();
    }
    float v = acc + bias[tid];
    v = (v >= 0.f) ? v : 0.01f * v;
    v += resid[(size_t)n * rstride + tid];
    size_t idx = (size_t)n * OUT + tid;
    if (WRITEO) out[idx] = v;
    if (SPLIT) {
        bf16 h, l; bf_split(v, h, l);
        outh[idx] = h; outl[idx] = l;
    }
}

// ---------------- driver ----------------
extern "C" void kernel_launch(void* const* d_in, const int* in_sizes, int n_in,
                              void* d_out, int out_size) {
    const float* x     = (const float*)d_in[0];
    const int*   eidx  = (const int*)d_in[1];
    const float* ea    = (const float*)d_in[2];
    const float* fa_w  = (const float*)d_in[3];
    const float* fa_b  = (const float*)d_in[4];
    const float* W1    = (const float*)d_in[5];
    const float* We1   = (const float*)d_in[6];
    const float* as1   = (const float*)d_in[7];
    const float* ad1   = (const float*)d_in[8];
    const float* ae1   = (const float*)d_in[9];
    const float* b1    = (const float*)d_in[10];
    const float* W2    = (const float*)d_in[11];
    const float* We2   = (const float*)d_in[12];
    const float* as2   = (const float*)d_in[13];
    const float* ad2   = (const float*)d_in[14];
    const float* ae2   = (const float*)d_in[15];
    const float* b2    = (const float*)d_in[16];
    const float* W3    = (const float*)d_in[17];
    const float* We3   = (const float*)d_in[18];
    const float* as3   = (const float*)d_in[19];
    const float* ad3   = (const float*)d_in[20];
    const float* ae3   = (const float*)d_in[21];
    const float* b3    = (const float*)d_in[22];
    const float* r1_w  = (const float*)d_in[23];
    const float* r1_b  = (const float*)d_in[24];
    const float* r2_w  = (const float*)d_in[25];
    const float* r2_b  = (const float*)d_in[26];
    const float* ffn_w1 = (const float*)d_in[27];
    const float* ffn_b1 = (const float*)d_in[28];
    const float* ffn_w2 = (const float*)d_in[29];
    const float* ffn_b2 = (const float*)d_in[30];
    float* out = (float*)d_out;

    const int* src = eidx;
    const int* dst = eidx + NE;

    bf16 *xh, *xl, *gxh, *gxl, *z1h, *z1l, *z2h, *z2l, *t64h, *t64l;
    bf16 *wfah, *wfal, *wb1h, *wb1l, *wb2h, *wb2l, *w3h, *w3l, *wf1h, *wf1l, *wf2h, *wf2l;
    float *hr, *zself, *h3, *bb1, *bb2;
    cudaGetSymbolAddress((void**)&xh, g_xh);   cudaGetSymbolAddress((void**)&xl, g_xl);
    cudaGetSymbolAddress((void**)&gxh, g_gxh); cudaGetSymbolAddress((void**)&gxl, g_gxl);
    cudaGetSymbolAddress((void**)&hr, g_hr);
    cudaGetSymbolAddress((void**)&z1h, g_z1h); cudaGetSymbolAddress((void**)&z1l, g_z1l);
    cudaGetSymbolAddress((void**)&z2h, g_z2h); cudaGetSymbolAddress((void**)&z2l, g_z2l);
    cudaGetSymbolAddress((void**)&t64h, g_t64h); cudaGetSymbolAddress((void**)&t64l, g_t64l);
    cudaGetSymbolAddress((void**)&zself, g_zself);
    cudaGetSymbolAddress((void**)&h3, g_h3);
    cudaGetSymbolAddress((void**)&wfah, g_wfa_h); cudaGetSymbolAddress((void**)&wfal, g_wfa_l);
    cudaGetSymbolAddress((void**)&wb1h, g_wb1_h); cudaGetSymbolAddress((void**)&wb1l, g_wb1_l);
    cudaGetSymbolAddress((void**)&wb2h, g_wb2_h); cudaGetSymbolAddress((void**)&wb2l, g_wb2_l);
    cudaGetSymbolAddress((void**)&w3h, g_w3_h);   cudaGetSymbolAddress((void**)&w3l, g_w3_l);
    cudaGetSymbolAddress((void**)&wf1h, g_wf1_h); cudaGetSymbolAddress((void**)&wf1l, g_wf1_l);
    cudaGetSymbolAddress((void**)&wf2h, g_wf2_h); cudaGetSymbolAddress((void**)&wf2l, g_wf2_l);
    cudaGetSymbolAddress((void**)&bb1, g_bb1);
    cudaGetSymbolAddress((void**)&bb2, g_bb2);

    cudaFuncSetAttribute(gemm5<EP_RELU, true, false>,
                         cudaFuncAttributeMaxDynamicSharedMemorySize, SMEM_DB);
    cudaFuncSetAttribute(gemm5<EP_NONE, false, true>,
                         cudaFuncAttributeMaxDynamicSharedMemorySize, SMEM_DB);
    cudaFuncSetAttribute(gemm6<EP_GATE, true, false>,
                         cudaFuncAttributeMaxDynamicSharedMemorySize, SMEM2);
    cudaFuncSetAttribute(gemm6<EP_NONE, false, true>,
                         cudaFuncAttributeMaxDynamicSharedMemorySize, SMEM2);

    const int TB = 256;
    const int nbN = (NN + TB - 1) / TB;
    const int nbE = (NE + TB - 1) / TB;
    const int gy = (NN + 127) / 128;

    // launch 1: weight prep for gate + layer1
    packall_kernel<<<(82944 + 255) / 256, 256>>>(fa_w, r1_w, W1, r1_b, r2_b);
    // launch 2: split x
    split_bf_kernel<<<(NN * 128 + 255) / 256, 256>>>(x, xh, xl, NN * 128);
    // launch 3: gate gemm (N=128, gemm6)
    gemm6<EP_GATE, true, false><<<dim3(1, gy), 128, SMEM2>>>(
        xh, xl, wfah, wfal, fa_b, x, nullptr, gxh, gxl, NN, 128, 128);
    // launch 4: layer-1 GEMM (N=512, gemm6)  <-- profiled launch
    gemm6<EP_NONE, false, true><<<dim3(4, gy), 128, SMEM2>>>(
        gxh, gxl, wb1h, wb1l, bb1, nullptr, hr, nullptr, nullptr, NN, 128, 512);

    // CSR build
    zero_kernel<<<nbN, TB>>>();
    deg_kernel<<<nbE, TB>>>(dst, ea);
    loop_kernel<<<nbN, TB>>>();
    alloc_kernel<<<(NN + 1023) / 1024, 1024>>>();
    csr_kernel<<<nbE, TB>>>(dst);

    // remaining weight packs
    packfuseT_kernel<<<(512 * 256 + 255) / 256, 256>>>(r2_w, W2, wb2h, wb2l, 256, 256);
    packT_kernel<<<(64 * 256 + 255) / 256, 256>>>(W3, w3h, w3l, 256, 64);
    packT_kernel<<<(64 * 128 + 255) / 256, 256>>>(ffn_w1, wf1h, wf1l, 128, 64);
    packT_kernel<<<(64 * 64 + 255) / 256, 256>>>(ffn_w2, wf2h, wf2l, 64, 64);

    // ffn path (N=64 -> gemm5)
    gemm5<EP_RELU, true, false><<<dim3(1, gy), 256, SMEM_DB>>>(
        gxh, gxl, wf1h, wf1l, ffn_b1, nullptr, nullptr, t64h, t64l, NN, 128, 64);
    gemm5<EP_NONE, false, true><<<dim3(1, gy), 256, SMEM_DB>>>(
        t64h, t64l, wf2h, wf2l, ffn_b2, nullptr, zself, nullptr, nullptr, NN, 64, 64);

    // layer 1 attention + aggregation
    attn_kernel<4><<<(NN * 4 * 32 + TB - 1) / TB, TB>>>(hr + 256, 512, as1, ad1);
    ch_kernel<<<1, 4>>>(We1, ae1, 4, 64);
    agg2<4, 64, true, false><<<NN, 256>>>(hr + 256, 512, src, ea, b1, hr, 512,
                                          nullptr, z1h, z1l);

    // layer 2 (gemm6)
    gemm6<EP_NONE, false, true><<<dim3(4, gy), 128, SMEM2>>>(
        z1h, z1l, wb2h, wb2l, bb2, nullptr, hr, nullptr, nullptr, NN, 256, 512);
    attn_kernel<4><<<(NN * 4 * 32 + TB - 1) / TB, TB>>>(hr + 256, 512, as2, ad2);
    ch_kernel<<<1, 4>>>(We2, ae2, 4, 64);
    agg2<4, 64, true, false><<<NN, 256>>>(hr + 256, 512, src, ea, b2, hr, 512,
                                          nullptr, z2h, z2l);

    // layer 3 (N=64 -> gemm5)
    gemm5<EP_NONE, false, true><<<dim3(1, gy), 256, SMEM_DB>>>(
        z2h, z2l, w3h, w3l, nullptr, nullptr, h3, nullptr, nullptr, NN, 256, 64);
    attn_kernel<1><<<(NN * 32 + TB - 1) / TB, TB>>>(h3, 64, as3, ad3);
    ch_kernel<<<1, 1>>>(We3, ae3, 1, 64);
    agg2<1, 64, false, true><<<NN, 64>>>(h3, 64, src, ea, b3, zself, 64,
                                         out, nullptr, nullptr);
}